// round 2
// baseline (speedup 1.0000x reference)
#include <cuda_runtime.h>

// Problem dims
#define Bb 4
#define Ss 256
#define Hh 768
#define Ff 32
#define Tt 256
#define WDd 64
#define Cc 16
#define HF 800          // H + F
#define BSr 1024        // B*S rows
#define NU 4096         // C*T

// Scratch (device globals: allocation-free)
__device__ float g_s  [BSr * Tt];        // 1 MB
__device__ float g_e  [BSr * Tt];        // 1 MB
__device__ float g_sU [BSr * NU];        // 16 MB   sU[row, c*256+u]
__device__ float g_sWs[BSr * Cc];
__device__ float g_eWe[BSr * Cc];
__device__ float g_whWw[Ss * Ss * Cc];   // 4 MB

// ---------------------------------------------------------------------------
// Kernel A: s = [fh|fv] @ start_W + start_b ; e likewise (blockIdx.z selects)
// Tiled SGEMM 64x64, 16x16 threads, 4x4 microtile, BK=32, K=800 (25 tiles)
// ---------------------------------------------------------------------------
__global__ void gemm_se(const float* __restrict__ fh, const float* __restrict__ fv,
                        const float* __restrict__ sW, const float* __restrict__ sb,
                        const float* __restrict__ eW, const float* __restrict__ eb)
{
    const float* W    = (blockIdx.z == 0) ? sW : eW;
    const float* bias = (blockIdx.z == 0) ? sb : eb;
    float* out        = (blockIdx.z == 0) ? g_s : g_e;

    __shared__ float As[32][68];   // As[k][m]
    __shared__ float Bs[32][68];   // Bs[k][n]

    const int tx = threadIdx.x, ty = threadIdx.y;
    const int tid = ty * 16 + tx;
    const int row0 = blockIdx.y * 64, col0 = blockIdx.x * 64;

    float acc[4][4] = {};

    for (int k0 = 0; k0 < HF; k0 += 32) {
#pragma unroll
        for (int l = 0; l < 8; l++) {
            int idx = tid + l * 256;
            int r = idx >> 5, kk = idx & 31;
            int row = row0 + r, k = k0 + kk;
            As[kk][r] = (k < Hh) ? fh[row * Hh + k] : fv[row * Ff + (k - Hh)];
        }
#pragma unroll
        for (int l = 0; l < 8; l++) {
            int idx = tid + l * 256;
            int kk = idx >> 6, c = idx & 63;
            Bs[kk][c] = W[(k0 + kk) * Tt + col0 + c];
        }
        __syncthreads();
#pragma unroll
        for (int kk = 0; kk < 32; kk++) {
            float4 a  = *reinterpret_cast<const float4*>(&As[kk][ty * 4]);
            float4 bb = *reinterpret_cast<const float4*>(&Bs[kk][tx * 4]);
            float av[4] = {a.x, a.y, a.z, a.w};
            float bv[4] = {bb.x, bb.y, bb.z, bb.w};
#pragma unroll
            for (int i = 0; i < 4; i++)
#pragma unroll
                for (int j = 0; j < 4; j++)
                    acc[i][j] += av[i] * bv[j];
        }
        __syncthreads();
    }

#pragma unroll
    for (int i = 0; i < 4; i++) {
        int r = row0 + ty * 4 + i;
#pragma unroll
        for (int j = 0; j < 4; j++) {
            int c = col0 + tx * 4 + j;
            out[r * Tt + c] = acc[i][j] + bias[c];
        }
    }
}

// ---------------------------------------------------------------------------
// Kernel B: sWs[row,c] = s[row,:]@Ws ; eWe[row,c] = e[row,:]@We  (tiny)
// ---------------------------------------------------------------------------
__global__ void proj_se(const float* __restrict__ linW)
{
    __shared__ float Wsh[2][Tt * Cc];   // 2 x 16 KB
    const int tid = threadIdx.x;
#pragma unroll
    for (int l = 0; l < 16; l++) {
        Wsh[0][tid + l * 256] = linW[tid + l * 256];                 // Ws rows [0,256)
        Wsh[1][tid + l * 256] = linW[Tt * Cc + tid + l * 256];       // We rows [256,512)
    }
    __syncthreads();

    int gid = blockIdx.x * 256 + tid;   // 0..16383
    int row = gid >> 4, c = gid & 15;
    float a0 = 0.f, a1 = 0.f;
#pragma unroll 4
    for (int t = 0; t < Tt; t++) {
        a0 += g_s[row * Tt + t] * Wsh[0][t * Cc + c];
        a1 += g_e[row * Tt + t] * Wsh[1][t * Cc + c];
    }
    g_sWs[gid] = a0;
    g_eWe[gid] = a1;
}

// ---------------------------------------------------------------------------
// Kernel C: whWw[p,c] = width_hidden[p,:]@Ww  (p = s*256+e), memory bound
// ---------------------------------------------------------------------------
__global__ void wh_proj(const float* __restrict__ wh, const float* __restrict__ linW)
{
    __shared__ float tileS[16 * WDd];     // 16 p-rows x 64
    __shared__ float WwS[WDd * Cc];       // 64 x 16
    const int tid = threadIdx.x;
    const int p0 = blockIdx.x * 16;
#pragma unroll
    for (int l = 0; l < 4; l++) {
        WwS[tid + l * 256]   = linW[2 * Tt * Cc + tid + l * 256];    // Ww rows [512,576)
        tileS[tid + l * 256] = wh[p0 * WDd + tid + l * 256];
    }
    __syncthreads();

    int pl = tid >> 4, c = tid & 15;
    float acc = 0.f;
#pragma unroll
    for (int w = 0; w < WDd; w++)
        acc += tileS[pl * WDd + w] * WwS[w * Cc + c];
    g_whWw[(p0 + pl) * Cc + c] = acc;
}

// ---------------------------------------------------------------------------
// Kernel D: sU[row, c*256+u] = sum_t s[row,t] * U[t,c,u]
// SGEMM (1024 x 4096 x 256), NN, same tiling as kernel A
// ---------------------------------------------------------------------------
__global__ void gemm_sU(const float* __restrict__ U)
{
    __shared__ float As[32][68];
    __shared__ float Bs[32][68];

    const int tx = threadIdx.x, ty = threadIdx.y;
    const int tid = ty * 16 + tx;
    const int row0 = blockIdx.y * 64, col0 = blockIdx.x * 64;

    float acc[4][4] = {};

    for (int k0 = 0; k0 < Tt; k0 += 32) {
#pragma unroll
        for (int l = 0; l < 8; l++) {
            int idx = tid + l * 256;
            int r = idx >> 5, kk = idx & 31;
            As[kk][r] = g_s[(row0 + r) * Tt + k0 + kk];
        }
#pragma unroll
        for (int l = 0; l < 8; l++) {
            int idx = tid + l * 256;
            int kk = idx >> 6, c = idx & 63;
            Bs[kk][c] = U[(k0 + kk) * NU + col0 + c];
        }
        __syncthreads();
#pragma unroll
        for (int kk = 0; kk < 32; kk++) {
            float4 a  = *reinterpret_cast<const float4*>(&As[kk][ty * 4]);
            float4 bb = *reinterpret_cast<const float4*>(&Bs[kk][tx * 4]);
            float av[4] = {a.x, a.y, a.z, a.w};
            float bv[4] = {bb.x, bb.y, bb.z, bb.w};
#pragma unroll
            for (int i = 0; i < 4; i++)
#pragma unroll
                for (int j = 0; j < 4; j++)
                    acc[i][j] += av[i] * bv[j];
        }
        __syncthreads();
    }

#pragma unroll
    for (int i = 0; i < 4; i++) {
        int r = row0 + ty * 4 + i;
#pragma unroll
        for (int j = 0; j < 4; j++)
            g_sU[r * NU + col0 + tx * 4 + j] = acc[i][j];
    }
}

// ---------------------------------------------------------------------------
// Kernel E: per batch b, C[i=(s,c), n=e] = sum_u sU_b[i,u] * e_b[n,u]  (NT GEMM)
// 4 x (4096 x 256 x 256). Epilogue fuses all FFN terms + bias, writes (b,s,e,c).
// ---------------------------------------------------------------------------
__global__ void gemm_pre(const float* __restrict__ lin_b, float* __restrict__ out)
{
    const int b = blockIdx.z;
    const float* A  = g_sU + (size_t)b * NU * Tt / 16 * 16;   // b * 4096*256
    const float* Bm = g_e + b * Ss * Tt;                      // (256,256) row-major

    __shared__ float As[32][68];   // As[k][i]
    __shared__ float Bs[32][68];   // Bs[k][n]

    const int tx = threadIdx.x, ty = threadIdx.y;
    const int tid = ty * 16 + tx;
    const int row0 = blockIdx.y * 64, col0 = blockIdx.x * 64;

    float acc[4][4] = {};

    for (int k0 = 0; k0 < Tt; k0 += 32) {
#pragma unroll
        for (int l = 0; l < 8; l++) {
            int idx = tid + l * 256;
            int r = idx >> 5, kk = idx & 31;
            As[kk][r] = A[(row0 + r) * Tt + k0 + kk];
        }
#pragma unroll
        for (int l = 0; l < 8; l++) {
            int idx = tid + l * 256;
            int r = idx >> 5, kk = idx & 31;
            Bs[kk][r] = Bm[(col0 + r) * Tt + k0 + kk];
        }
        __syncthreads();
#pragma unroll
        for (int kk = 0; kk < 32; kk++) {
            float4 a  = *reinterpret_cast<const float4*>(&As[kk][ty * 4]);
            float4 bb = *reinterpret_cast<const float4*>(&Bs[kk][tx * 4]);
            float av[4] = {a.x, a.y, a.z, a.w};
            float bv[4] = {bb.x, bb.y, bb.z, bb.w};
#pragma unroll
            for (int i = 0; i < 4; i++)
#pragma unroll
                for (int j = 0; j < 4; j++)
                    acc[i][j] += av[i] * bv[j];
        }
        __syncthreads();
    }

#pragma unroll
    for (int i = 0; i < 4; i++) {
        int gi = row0 + ty * 4 + i;          // gi = s*16 + c
        int s = gi >> 4, c = gi & 15;
        float fs = g_sWs[(b * Ss + s) * Cc + c];
        float lb = lin_b[c];
#pragma unroll
        for (int j = 0; j < 4; j++) {
            int n = col0 + tx * 4 + j;       // e index
            out[(((size_t)(b * Ss + s) * Ss) + n) * Cc + c] =
                acc[i][j] + fs + g_eWe[(b * Ss + n) * Cc + c]
                          + g_whWw[(s * Ss + n) * Cc + c] + lb;
        }
    }
}

// ---------------------------------------------------------------------------
extern "C" void kernel_launch(void* const* d_in, const int* in_sizes, int n_in,
                              void* d_out, int out_size)
{
    const float* fh   = (const float*)d_in[0];   // final_hidden (4,256,768)
    const float* fv   = (const float*)d_in[1];   // feature_vecs (4,256,32)
    const float* sW   = (const float*)d_in[2];   // start_W (800,256)
    const float* sb   = (const float*)d_in[3];   // start_b (256)
    const float* eW   = (const float*)d_in[4];   // end_W (800,256)
    const float* eb   = (const float*)d_in[5];   // end_b (256)
    const float* U    = (const float*)d_in[6];   // U (256,16,256)
    const float* wh   = (const float*)d_in[7];   // width_hidden (256,256,64)
    const float* linW = (const float*)d_in[8];   // lin_W (576,16)
    const float* linb = (const float*)d_in[9];   // lin_b (16)
    float* out = (float*)d_out;                  // (4,256,256,16) f32

    dim3 blk(16, 16);

    gemm_se<<<dim3(4, 16, 2), blk>>>(fh, fv, sW, sb, eW, eb);
    wh_proj<<<4096, 256>>>(wh, linW);
    proj_se<<<64, 256>>>(linW);
    gemm_sU<<<dim3(64, 16), blk>>>(U);
    gemm_pre<<<dim3(4, 64, 4), blk>>>(linb, out);
}

// round 4
// speedup vs baseline: 1.1857x; 1.1857x over previous
#include <cuda_runtime.h>
#include <cuda_bf16.h>
#include <cstdint>

#define Hh 768
#define Ff 32
#define Tt 256
#define HF 800
#define BSr 1024
#define NU 4096
#define Cc 16
#define WDd 64
#define Ss 256

// ------------------------------- scratch (device globals, allocation-free)
__device__ __align__(256) __nv_bfloat16 g_xh [BSr * HF],  g_xl [BSr * HF];
__device__ __align__(256) __nv_bfloat16 g_Wth[512 * HF],  g_Wtl[512 * HF];
__device__ __align__(256) __nv_bfloat16 g_Uth[NU * Tt],   g_Utl[NU * Tt];
__device__ __align__(256) __nv_bfloat16 g_sh [BSr * Tt],  g_sl [BSr * Tt];
__device__ __align__(256) __nv_bfloat16 g_eh [BSr * Tt],  g_el [BSr * Tt];
__device__ __align__(256) __nv_bfloat16 g_sUh[BSr * NU],  g_sUl[BSr * NU];
__device__ float g_s  [BSr * Tt];
__device__ float g_e  [BSr * Tt];
__device__ float g_sWs[BSr * Cc];
__device__ float g_eWe[BSr * Cc];
__device__ float g_whWw[Ss * Ss * Cc];

// ------------------------------- PTX helpers (baseline sm_100 ISA only)
__device__ __forceinline__ uint32_t smem_u32(const void* p) {
    uint32_t a;
    asm("{ .reg .u64 t; cvta.to.shared.u64 t, %1; cvt.u32.u64 %0, t; }" : "=r"(a) : "l"(p));
    return a;
}
__device__ __forceinline__ void cpa16(uint32_t dst, const void* src) {
    asm volatile("cp.async.cg.shared.global [%0], [%1], 16;" :: "r"(dst), "l"(src));
}
#define CP_COMMIT() asm volatile("cp.async.commit_group;" ::: "memory")
#define CP_WAIT(n)  asm volatile("cp.async.wait_group %0;" :: "n"(n) : "memory")

__device__ __forceinline__ void ldsm4(uint32_t& r0, uint32_t& r1, uint32_t& r2, uint32_t& r3, uint32_t a) {
    asm volatile("ldmatrix.sync.aligned.m8n8.x4.shared.b16 {%0,%1,%2,%3}, [%4];"
                 : "=r"(r0), "=r"(r1), "=r"(r2), "=r"(r3) : "r"(a));
}
__device__ __forceinline__ void mma_bf16(float* c, const uint32_t* a, const uint32_t* b) {
    asm volatile("mma.sync.aligned.m16n8k16.row.col.f32.bf16.bf16.f32 "
                 "{%0,%1,%2,%3},{%4,%5,%6,%7},{%8,%9},{%0,%1,%2,%3};"
                 : "+f"(c[0]), "+f"(c[1]), "+f"(c[2]), "+f"(c[3])
                 : "r"(a[0]), "r"(a[1]), "r"(a[2]), "r"(a[3]), "r"(b[0]), "r"(b[1]));
}
__device__ __forceinline__ void split2(float v, __nv_bfloat16& hi, __nv_bfloat16& lo) {
    hi = __float2bfloat16(v);
    lo = __float2bfloat16(v - __bfloat162float(hi));
}

// ------------------------------- GEMM config
// CTA tile 128x128, BK=32, 8 warps (2m x 4n), warp tile 64x32, 3-stage cp.async.
// Operands pre-split to bf16 (hi,lo); accumulate 3 products: hh + hl + lh.
constexpr int BK = 32;
constexpr int STG = 3;
constexpr int LDS_ST = 40;                 // padded stride (elems): 80B, LDSM conflict-free
constexpr int TILE_B = 128 * LDS_ST * 2;   // 10240 B
constexpr int STAGE_B = 4 * TILE_B;        // Ah, Al, Bh, Bl
constexpr int SMEM_B = STG * STAGE_B;      // 122880 B

// EPI: 0 = s/e projection (N=512 fused), 1 = sU, 2 = pre (fully fused epilogue)
template<int EPI>
__global__ void __launch_bounds__(256, 1)
mma_gemm(const float* __restrict__ p0, const float* __restrict__ p1,
         float* __restrict__ outp, int K)
{
    extern __shared__ char sm[];
    const uint32_t smb = smem_u32(sm);
    const int tid = threadIdx.x, lane = tid & 31, w = tid >> 5;
    const int wm = w >> 2, wn = w & 3;

    int m0, n0;
    const __nv_bfloat16 *Ah, *Al, *Bh, *Bl;
    int ld;
    if (EPI == 0) {
        m0 = blockIdx.y * 128; n0 = blockIdx.x * 128; ld = HF;
        Ah = g_xh + (size_t)m0 * HF;  Al = g_xl + (size_t)m0 * HF;
        Bh = g_Wth + (size_t)n0 * HF; Bl = g_Wtl + (size_t)n0 * HF;
    } else if (EPI == 1) {
        m0 = blockIdx.y * 128; n0 = blockIdx.x * 128; ld = Tt;
        Ah = g_sh + (size_t)m0 * Tt;  Al = g_sl + (size_t)m0 * Tt;
        Bh = g_Uth + (size_t)n0 * Tt; Bl = g_Utl + (size_t)n0 * Tt;
    } else {
        const int b = blockIdx.z;
        m0 = b * 4096 + blockIdx.y * 128; n0 = blockIdx.x * 128; ld = Tt;
        Ah = g_sUh + (size_t)m0 * Tt; Al = g_sUl + (size_t)m0 * Tt;
        Bh = g_eh + (size_t)b * Ss * Tt + (size_t)n0 * Tt;
        Bl = g_el + (size_t)b * Ss * Tt + (size_t)n0 * Tt;
    }
    const __nv_bfloat16* srcs[4] = {Ah, Al, Bh, Bl};

    float acc[4][4][4] = {};
    const int nk = K / BK;

    auto load_stage = [&](int st, int kb) {
        const uint32_t sbase = smb + st * STAGE_B;
        const int kc = kb * BK;
#pragma unroll
        for (int t = 0; t < 4; t++) {
#pragma unroll
            for (int j = 0; j < 2; j++) {
                int id = tid * 2 + j;            // 0..511
                int row = id >> 2, ch = id & 3;  // 128 rows x 4 x 16B
                const void* src = srcs[t] + (size_t)row * ld + kc + ch * 8;
                cpa16(sbase + t * TILE_B + row * 80 + ch * 16, src);
            }
        }
    };

    for (int s = 0; s < STG - 1 && s < nk; s++) { load_stage(s, s); CP_COMMIT(); }

    for (int kb = 0; kb < nk; kb++) {
        CP_WAIT(STG - 2);
        __syncthreads();

        const uint32_t base = smb + (kb % STG) * STAGE_B;
        const uint32_t aH = base, aL = base + TILE_B, bH = base + 2 * TILE_B, bL = base + 3 * TILE_B;
#pragma unroll
        for (int ks = 0; ks < 2; ks++) {
            const uint32_t aoff = (uint32_t)(wm * 64 + (lane & 15)) * 80 + ks * 32 + (lane >> 4) * 16;
            uint32_t AHf[4][4], ALf[4][4];
#pragma unroll
            for (int mi = 0; mi < 4; mi++) {
                ldsm4(AHf[mi][0], AHf[mi][1], AHf[mi][2], AHf[mi][3], aH + aoff + mi * 16 * 80);
                ldsm4(ALf[mi][0], ALf[mi][1], ALf[mi][2], ALf[mi][3], aL + aoff + mi * 16 * 80);
            }
            const uint32_t boff = (uint32_t)(wn * 32 + ((lane >> 4) << 3) + (lane & 7)) * 80
                                + ks * 32 + ((lane >> 3) & 1) * 16;
            uint32_t BHf[8], BLf[8];
            ldsm4(BHf[0], BHf[1], BHf[2], BHf[3], bH + boff);
            ldsm4(BHf[4], BHf[5], BHf[6], BHf[7], bH + boff + 16 * 80);
            ldsm4(BLf[0], BLf[1], BLf[2], BLf[3], bL + boff);
            ldsm4(BLf[4], BLf[5], BLf[6], BLf[7], bL + boff + 16 * 80);
#pragma unroll
            for (int mi = 0; mi < 4; mi++)
#pragma unroll
                for (int ni = 0; ni < 4; ni++)
                    mma_bf16(acc[mi][ni], AHf[mi], &BHf[2 * ni]);
#pragma unroll
            for (int mi = 0; mi < 4; mi++)
#pragma unroll
                for (int ni = 0; ni < 4; ni++)
                    mma_bf16(acc[mi][ni], AHf[mi], &BLf[2 * ni]);
#pragma unroll
            for (int mi = 0; mi < 4; mi++)
#pragma unroll
                for (int ni = 0; ni < 4; ni++)
                    mma_bf16(acc[mi][ni], ALf[mi], &BHf[2 * ni]);
        }
        __syncthreads();
        const int nx = kb + STG - 1;
        if (nx < nk) load_stage(nx % STG, nx);
        CP_COMMIT();
    }

    // ------------- epilogue
#pragma unroll
    for (int mi = 0; mi < 4; mi++) {
#pragma unroll
        for (int ni = 0; ni < 4; ni++) {
#pragma unroll
            for (int r = 0; r < 4; r++) {
                const int ml = wm * 64 + mi * 16 + (lane >> 2) + ((r >> 1) ? 8 : 0);
                const int nl = wn * 32 + ni * 8 + 2 * (lane & 3) + (r & 1);
                float v = acc[mi][ni][r];
                if (EPI == 0) {
                    const int m = m0 + ml, n = n0 + nl;
                    __nv_bfloat16 hi, lo;
                    if (n < 256) {
                        v += p0[n];
                        split2(v, hi, lo);
                        g_s [m * Tt + n] = v;
                        g_sh[m * Tt + n] = hi;
                        g_sl[m * Tt + n] = lo;
                    } else {
                        const int nn = n - 256;
                        v += p1[nn];
                        split2(v, hi, lo);
                        g_e [m * Tt + nn] = v;
                        g_eh[m * Tt + nn] = hi;
                        g_el[m * Tt + nn] = lo;
                    }
                } else if (EPI == 1) {
                    const int m = m0 + ml, n = n0 + nl;
                    __nv_bfloat16 hi, lo;
                    split2(v, hi, lo);
                    g_sUh[(size_t)m * NU + n] = hi;
                    g_sUl[(size_t)m * NU + n] = lo;
                } else {
                    const int m = m0 + ml, n = n0 + nl;     // m = b*4096 + s*16 + c
                    const int b = m >> 12, c = m & 15, s = (m >> 4) & 255;
                    v += g_sWs[m] + p0[c]
                       + g_eWe[(b << 12) + (n << 4) + c]
                       + g_whWw[(((s << 8) + n) << 4) + c];
                    outp[((size_t)((b << 8) + s) * 256 + n) * 16 + c] = v;
                }
            }
        }
    }
}

// ------------------------------- prep kernels
__global__ void pack_split_x(const float* __restrict__ fh, const float* __restrict__ fv) {
    const int row = blockIdx.x;
    for (int k = threadIdx.x; k < HF; k += 256) {
        float v = (k < Hh) ? fh[(size_t)row * Hh + k] : fv[(size_t)row * Ff + k - Hh];
        __nv_bfloat16 hi, lo;
        split2(v, hi, lo);
        g_xh[(size_t)row * HF + k] = hi;
        g_xl[(size_t)row * HF + k] = lo;
    }
}
// transpose src[R][C] -> dst[C][R] with bf16 hi/lo split
__global__ void transp_split(const float* __restrict__ src,
                             __nv_bfloat16* __restrict__ dh, __nv_bfloat16* __restrict__ dl,
                             int R, int C) {
    __shared__ float t[32][33];
    const int bx = blockIdx.x * 32, by = blockIdx.y * 32;
    const int tx = threadIdx.x, ty = threadIdx.y;
#pragma unroll
    for (int j = 0; j < 32; j += 8)
        t[ty + j][tx] = src[(size_t)(by + ty + j) * C + bx + tx];
    __syncthreads();
#pragma unroll
    for (int j = 0; j < 32; j += 8) {
        float v = t[tx][ty + j];                  // src[by+tx][bx+ty+j]
        const int r = by + tx, c = bx + ty + j;
        __nv_bfloat16 hi, lo;
        split2(v, hi, lo);
        dh[(size_t)c * R + r] = hi;
        dl[(size_t)c * R + r] = lo;
    }
}
__global__ void proj_se(const float* __restrict__ linW) {
    __shared__ float Wsh[2][Tt * Cc];
    const int tid = threadIdx.x;
#pragma unroll
    for (int l = 0; l < 16; l++) {
        Wsh[0][tid + l * 256] = linW[tid + l * 256];
        Wsh[1][tid + l * 256] = linW[Tt * Cc + tid + l * 256];
    }
    __syncthreads();
    const int gid = blockIdx.x * 256 + tid;
    const int row = gid >> 4, c = gid & 15;
    float a0 = 0.f, a1 = 0.f;
#pragma unroll 4
    for (int t = 0; t < Tt; t++) {
        a0 += g_s[row * Tt + t] * Wsh[0][t * Cc + c];
        a1 += g_e[row * Tt + t] * Wsh[1][t * Cc + c];
    }
    g_sWs[gid] = a0;
    g_eWe[gid] = a1;
}
__global__ void wh_proj(const float* __restrict__ wh, const float* __restrict__ linW) {
    __shared__ float tileS[16 * WDd];
    __shared__ float WwS[WDd * Cc];
    const int tid = threadIdx.x;
    const int p0 = blockIdx.x * 16;
#pragma unroll
    for (int l = 0; l < 4; l++) {
        WwS[tid + l * 256]   = linW[2 * Tt * Cc + tid + l * 256];
        tileS[tid + l * 256] = wh[(size_t)p0 * WDd + tid + l * 256];
    }
    __syncthreads();
    const int pl = tid >> 4, c = tid & 15;
    float acc = 0.f;
#pragma unroll
    for (int w = 0; w < WDd; w++)
        acc += tileS[pl * WDd + w] * WwS[w * Cc + c];
    g_whWw[(p0 + pl) * Cc + c] = acc;
}

// ------------------------------- launch
extern "C" void kernel_launch(void* const* d_in, const int* in_sizes, int n_in,
                              void* d_out, int out_size)
{
    const float* fh   = (const float*)d_in[0];
    const float* fv   = (const float*)d_in[1];
    const float* sW   = (const float*)d_in[2];
    const float* sb   = (const float*)d_in[3];
    const float* eW   = (const float*)d_in[4];
    const float* eb   = (const float*)d_in[5];
    const float* U    = (const float*)d_in[6];
    const float* wh   = (const float*)d_in[7];
    const float* linW = (const float*)d_in[8];
    const float* linb = (const float*)d_in[9];
    float* out = (float*)d_out;

    cudaFuncSetAttribute(mma_gemm<0>, cudaFuncAttributeMaxDynamicSharedMemorySize, SMEM_B);
    cudaFuncSetAttribute(mma_gemm<1>, cudaFuncAttributeMaxDynamicSharedMemorySize, SMEM_B);
    cudaFuncSetAttribute(mma_gemm<2>, cudaFuncAttributeMaxDynamicSharedMemorySize, SMEM_B);

    __nv_bfloat16 *pWth, *pWtl, *pUth, *pUtl;
    cudaGetSymbolAddress((void**)&pWth, g_Wth);
    cudaGetSymbolAddress((void**)&pWtl, g_Wtl);
    cudaGetSymbolAddress((void**)&pUth, g_Uth);
    cudaGetSymbolAddress((void**)&pUtl, g_Utl);

    dim3 tb(32, 8);
    pack_split_x<<<1024, 256>>>(fh, fv);
    transp_split<<<dim3(8, 25),  tb>>>(sW, pWth, pWtl, HF, Tt);
    transp_split<<<dim3(8, 25),  tb>>>(eW, pWth + 256 * HF, pWtl + 256 * HF, HF, Tt);
    transp_split<<<dim3(128, 8), tb>>>(U, pUth, pUtl, Tt, NU);
    wh_proj<<<4096, 256>>>(wh, linW);

    mma_gemm<0><<<dim3(4, 8),     256, SMEM_B>>>(sb, eb, nullptr, HF);   // s,e = x@W + b
    proj_se<<<64, 256>>>(linW);
    mma_gemm<1><<<dim3(32, 8),    256, SMEM_B>>>(nullptr, nullptr, nullptr, Tt); // sU
    mma_gemm<2><<<dim3(2, 32, 4), 256, SMEM_B>>>(linb, nullptr, out, Tt);        // pre + fused FFN
}

// round 5
// speedup vs baseline: 1.8546x; 1.5641x over previous
#include <cuda_runtime.h>
#include <cuda_bf16.h>
#include <cstdint>

#define Hh 768
#define Ff 32
#define Tt 256
#define HF 800
#define BSr 1024
#define NU 4096
#define Cc 16
#define WDd 64
#define Ss 256

// ------------------------------- scratch (device globals)
__device__ __align__(256) __nv_bfloat16 g_xh [BSr * HF],  g_xl [BSr * HF];
__device__ __align__(256) __nv_bfloat16 g_Wth[512 * HF],  g_Wtl[512 * HF];
__device__ __align__(256) __nv_bfloat16 g_Uth[NU * Tt],   g_Utl[NU * Tt];
__device__ __align__(256) __nv_bfloat16 g_sh [BSr * Tt],  g_sl [BSr * Tt];
__device__ __align__(256) __nv_bfloat16 g_eh [BSr * Tt],  g_el [BSr * Tt];
__device__ __align__(256) __nv_bfloat16 g_sUh[BSr * NU],  g_sUl[BSr * NU];
__device__ float g_sWs[BSr * Cc];
__device__ float g_eWe[BSr * Cc];
__device__ float g_whWw[Ss * Ss * Cc];

// ------------------------------- PTX helpers (baseline sm_100 ISA only)
__device__ __forceinline__ uint32_t smem_u32(const void* p) {
    uint32_t a;
    asm("{ .reg .u64 t; cvta.to.shared.u64 t, %1; cvt.u32.u64 %0, t; }" : "=r"(a) : "l"(p));
    return a;
}
__device__ __forceinline__ void cpa16(uint32_t dst, const void* src) {
    asm volatile("cp.async.cg.shared.global [%0], [%1], 16;" :: "r"(dst), "l"(src));
}
#define CP_COMMIT() asm volatile("cp.async.commit_group;" ::: "memory")
#define CP_WAIT(n)  asm volatile("cp.async.wait_group %0;" :: "n"(n) : "memory")

__device__ __forceinline__ void ldsm4(uint32_t& r0, uint32_t& r1, uint32_t& r2, uint32_t& r3, uint32_t a) {
    asm volatile("ldmatrix.sync.aligned.m8n8.x4.shared.b16 {%0,%1,%2,%3}, [%4];"
                 : "=r"(r0), "=r"(r1), "=r"(r2), "=r"(r3) : "r"(a));
}
__device__ __forceinline__ void mma_bf16(float* c, const uint32_t* a, const uint32_t* b) {
    asm volatile("mma.sync.aligned.m16n8k16.row.col.f32.bf16.bf16.f32 "
                 "{%0,%1,%2,%3},{%4,%5,%6,%7},{%8,%9},{%0,%1,%2,%3};"
                 : "+f"(c[0]), "+f"(c[1]), "+f"(c[2]), "+f"(c[3])
                 : "r"(a[0]), "r"(a[1]), "r"(a[2]), "r"(a[3]), "r"(b[0]), "r"(b[1]));
}
__device__ __forceinline__ void split2(float v, __nv_bfloat16& hi, __nv_bfloat16& lo) {
    hi = __float2bfloat16(v);
    lo = __float2bfloat16(v - __bfloat162float(hi));
}
__device__ __forceinline__ uint32_t pk2(__nv_bfloat16 a, __nv_bfloat16 b) {
    __nv_bfloat162 t = __halves2bfloat162(a, b);
    return *reinterpret_cast<uint32_t*>(&t);
}

constexpr int STG = 3;

// ---------------------------------------------------------------------------
// NT GEMM bf16x3: D[MT x 128] = A[MT x K] * B[128 x K]^T
// 8 warps (2m x 4n), warp tile (MT/2) x 32. Single-barrier 3-stage pipeline.
// Epilogue staged through SMEM for coalesced global I/O.
// EPI: 0 = s/e projection, 1 = sU, 2 = pre (+ fused FFN terms)
// ---------------------------------------------------------------------------
template<int MT, int EPI>
__global__ void __launch_bounds__(256, 1)
mma_gemm(const float* __restrict__ p0, const float* __restrict__ p1,
         float* __restrict__ outp, int K)
{
    constexpr int TA = MT * 80;          // bytes per A variant per stage
    constexpr int TB = 128 * 80;
    constexpr int STAGE = 2 * TA + 2 * TB;
    constexpr int MI = MT / 32;

    extern __shared__ char sm[];
    const uint32_t smb = smem_u32(sm);
    const int tid = threadIdx.x, lane = tid & 31, w = tid >> 5;
    const int wm = w >> 2, wn = w & 3;

    int m0, n0;
    const __nv_bfloat16 *Ah, *Al, *Bh, *Bl;
    int ld;
    if (EPI == 0) {
        m0 = blockIdx.y * MT; n0 = blockIdx.x * 128; ld = HF;
        Ah = g_xh + (size_t)m0 * HF;  Al = g_xl + (size_t)m0 * HF;
        Bh = g_Wth + (size_t)n0 * HF; Bl = g_Wtl + (size_t)n0 * HF;
    } else if (EPI == 1) {
        m0 = blockIdx.y * MT; n0 = blockIdx.x * 128; ld = Tt;
        Ah = g_sh + (size_t)m0 * Tt;  Al = g_sl + (size_t)m0 * Tt;
        Bh = g_Uth + (size_t)n0 * Tt; Bl = g_Utl + (size_t)n0 * Tt;
    } else {
        const int b = blockIdx.z;
        m0 = b * 4096 + blockIdx.y * MT; n0 = blockIdx.x * 128; ld = Tt;
        Ah = g_sUh + (size_t)m0 * Tt; Al = g_sUl + (size_t)m0 * Tt;
        Bh = g_eh + (size_t)b * Ss * Tt + (size_t)n0 * Tt;
        Bl = g_el + (size_t)b * Ss * Tt + (size_t)n0 * Tt;
    }

    float acc[MI][4][4] = {};
    const int nk = K / 32;

    auto load_stage = [&](int st, int kb) {
        const uint32_t sb = smb + st * STAGE;
        const int kc = kb * 32;
#pragma unroll
        for (int i = tid; i < MT * 4; i += 256) {
            const int row = i >> 2, ch = i & 3;
            const size_t off = (size_t)row * ld + kc + ch * 8;
            cpa16(sb + row * 80 + ch * 16,      Ah + off);
            cpa16(sb + TA + row * 80 + ch * 16, Al + off);
        }
#pragma unroll
        for (int i = tid; i < 512; i += 256) {
            const int row = i >> 2, ch = i & 3;
            const size_t off = (size_t)row * ld + kc + ch * 8;
            cpa16(sb + 2 * TA + row * 80 + ch * 16,      Bh + off);
            cpa16(sb + 2 * TA + TB + row * 80 + ch * 16, Bl + off);
        }
    };

    load_stage(0, 0); CP_COMMIT();
    load_stage(1, 1); CP_COMMIT();

    for (int kb = 0; kb < nk; kb++) {
        CP_WAIT(1);
        __syncthreads();
        const int nx = kb + STG - 1;
        if (nx < nk) load_stage(nx % STG, nx);
        CP_COMMIT();

        const uint32_t base = smb + (kb % STG) * STAGE;
        const uint32_t aH = base, aL = base + TA;
        const uint32_t bH = base + 2 * TA, bL = base + 2 * TA + TB;
#pragma unroll
        for (int ks = 0; ks < 2; ks++) {
            const uint32_t aoff = (uint32_t)(wm * (MT / 2) + (lane & 15)) * 80
                                + ks * 32 + (lane >> 4) * 16;
            uint32_t AHf[MI][4], ALf[MI][4];
#pragma unroll
            for (int mi = 0; mi < MI; mi++) {
                ldsm4(AHf[mi][0], AHf[mi][1], AHf[mi][2], AHf[mi][3], aH + aoff + mi * 16 * 80);
                ldsm4(ALf[mi][0], ALf[mi][1], ALf[mi][2], ALf[mi][3], aL + aoff + mi * 16 * 80);
            }
            const uint32_t boff = (uint32_t)(wn * 32 + ((lane >> 4) << 3) + (lane & 7)) * 80
                                + ks * 32 + ((lane >> 3) & 1) * 16;
            uint32_t BHf[8], BLf[8];
            ldsm4(BHf[0], BHf[1], BHf[2], BHf[3], bH + boff);
            ldsm4(BHf[4], BHf[5], BHf[6], BHf[7], bH + boff + 16 * 80);
            ldsm4(BLf[0], BLf[1], BLf[2], BLf[3], bL + boff);
            ldsm4(BLf[4], BLf[5], BLf[6], BLf[7], bL + boff + 16 * 80);
#pragma unroll
            for (int mi = 0; mi < MI; mi++)
#pragma unroll
                for (int ni = 0; ni < 4; ni++)
                    mma_bf16(acc[mi][ni], AHf[mi], &BHf[2 * ni]);
#pragma unroll
            for (int mi = 0; mi < MI; mi++)
#pragma unroll
                for (int ni = 0; ni < 4; ni++)
                    mma_bf16(acc[mi][ni], AHf[mi], &BLf[2 * ni]);
#pragma unroll
            for (int mi = 0; mi < MI; mi++)
#pragma unroll
                for (int ni = 0; ni < 4; ni++)
                    mma_bf16(acc[mi][ni], ALf[mi], &BHf[2 * ni]);
        }
    }

    // ---------------- epilogue: stage C in SMEM, then coalesced global I/O
    __syncthreads();
    float* Cp = reinterpret_cast<float*>(sm);   // [MT][132]
#pragma unroll
    for (int mi = 0; mi < MI; mi++)
#pragma unroll
        for (int ni = 0; ni < 4; ni++)
#pragma unroll
            for (int r = 0; r < 4; r++) {
                const int ml = wm * (MT / 2) + mi * 16 + (lane >> 2) + ((r >> 1) ? 8 : 0);
                const int nl = wn * 32 + ni * 8 + 2 * (lane & 3) + (r & 1);
                Cp[ml * 132 + nl] = acc[mi][ni][r];
            }
    __syncthreads();

    if (EPI == 0) {
        constexpr int NF4 = MT * 32;
#pragma unroll
        for (int i = tid; i < NF4; i += 256) {
            const int ml = i >> 5, j4 = (i & 31) << 2;
            float4 v = *reinterpret_cast<float4*>(&Cp[ml * 132 + j4]);
            const int n = n0 + j4;
            const float* bias;
            __nv_bfloat16 *dh, *dl;
            int nc;
            if (n < 256) { bias = p0; dh = g_sh; dl = g_sl; nc = n; }
            else         { bias = p1; dh = g_eh; dl = g_el; nc = n - 256; }
            v.x += bias[nc]; v.y += bias[nc + 1]; v.z += bias[nc + 2]; v.w += bias[nc + 3];
            __nv_bfloat16 hx, lx, hy, ly, hz, lz, hw, lw;
            split2(v.x, hx, lx); split2(v.y, hy, ly);
            split2(v.z, hz, lz); split2(v.w, hw, lw);
            const size_t o = (size_t)(m0 + ml) * Tt + nc;
            *reinterpret_cast<uint2*>(&dh[o]) = make_uint2(pk2(hx, hy), pk2(hz, hw));
            *reinterpret_cast<uint2*>(&dl[o]) = make_uint2(pk2(lx, ly), pk2(lz, lw));
        }
    } else if (EPI == 1) {
        constexpr int NF4 = MT * 32;
#pragma unroll
        for (int i = tid; i < NF4; i += 256) {
            const int ml = i >> 5, j4 = (i & 31) << 2;
            float4 v = *reinterpret_cast<float4*>(&Cp[ml * 132 + j4]);
            __nv_bfloat16 hx, lx, hy, ly, hz, lz, hw, lw;
            split2(v.x, hx, lx); split2(v.y, hy, ly);
            split2(v.z, hz, lz); split2(v.w, hw, lw);
            const size_t o = (size_t)(m0 + ml) * NU + n0 + j4;
            *reinterpret_cast<uint2*>(&g_sUh[o]) = make_uint2(pk2(hx, hy), pk2(hz, hw));
            *reinterpret_cast<uint2*>(&g_sUl[o]) = make_uint2(pk2(lx, ly), pk2(lz, lw));
        }
    } else {
        const int b = m0 >> 12;
        const int s_base = (m0 >> 4) & 255;
#pragma unroll
        for (int sl_ = 0; sl_ < MT / 16; sl_++) {
            const int s = s_base + sl_;
            float* obase = outp + (((size_t)(b * 256 + s)) * 256 + n0) * 16;
            const float* eweB = g_eWe + (b << 12) + (n0 << 4);
            const float* whB  = g_whWw + (((s << 8) + n0) << 4);
            const float* swB  = g_sWs + m0 + sl_ * 16;
#pragma unroll
            for (int i = tid; i < 512; i += 256) {
                const int e = i >> 2, cq = (i & 3) << 2;
                const int mrow = sl_ * 16 + cq;
                float4 v;
                v.x = Cp[(mrow + 0) * 132 + e];
                v.y = Cp[(mrow + 1) * 132 + e];
                v.z = Cp[(mrow + 2) * 132 + e];
                v.w = Cp[(mrow + 3) * 132 + e];
                float4 ew = *reinterpret_cast<const float4*>(&eweB[e * 16 + cq]);
                float4 wv = *reinterpret_cast<const float4*>(&whB[e * 16 + cq]);
                float4 sw = *reinterpret_cast<const float4*>(&swB[cq]);
                float4 lb = *reinterpret_cast<const float4*>(&p0[cq]);
                v.x += ew.x + wv.x + sw.x + lb.x;
                v.y += ew.y + wv.y + sw.y + lb.y;
                v.z += ew.z + wv.z + sw.z + lb.z;
                v.w += ew.w + wv.w + sw.w + lb.w;
                *reinterpret_cast<float4*>(&obase[e * 16 + cq]) = v;
            }
        }
    }
}

// ------------------------------- prep kernels
__global__ void pack_split_x(const float* __restrict__ fh, const float* __restrict__ fv) {
    const int row = blockIdx.x;
    for (int k = threadIdx.x; k < HF; k += 256) {
        float v = (k < Hh) ? fh[(size_t)row * Hh + k] : fv[(size_t)row * Ff + k - Hh];
        __nv_bfloat16 hi, lo;
        split2(v, hi, lo);
        g_xh[(size_t)row * HF + k] = hi;
        g_xl[(size_t)row * HF + k] = lo;
    }
}
__global__ void transp_split(const float* __restrict__ src,
                             __nv_bfloat16* __restrict__ dh, __nv_bfloat16* __restrict__ dl,
                             int R, int C) {
    __shared__ float t[32][33];
    const int bx = blockIdx.x * 32, by = blockIdx.y * 32;
    const int tx = threadIdx.x, ty = threadIdx.y;
#pragma unroll
    for (int j = 0; j < 32; j += 8)
        t[ty + j][tx] = src[(size_t)(by + ty + j) * C + bx + tx];
    __syncthreads();
#pragma unroll
    for (int j = 0; j < 32; j += 8) {
        float v = t[tx][ty + j];
        const int r = by + tx, c = bx + ty + j;
        __nv_bfloat16 hi, lo;
        split2(v, hi, lo);
        dh[(size_t)c * R + r] = hi;
        dl[(size_t)c * R + r] = lo;
    }
}
__global__ void proj_se(const float* __restrict__ linW) {
    __shared__ float Wsh[2][Tt * Cc];
    const int tid = threadIdx.x;
#pragma unroll
    for (int l = 0; l < 16; l++) {
        Wsh[0][tid + l * 256] = linW[tid + l * 256];
        Wsh[1][tid + l * 256] = linW[Tt * Cc + tid + l * 256];
    }
    __syncthreads();
    const int gid = blockIdx.x * 256 + tid;
    const int row = gid >> 4, c = gid & 15;
    float a0 = 0.f, a1 = 0.f;
#pragma unroll 4
    for (int t = 0; t < Tt; t++) {
        const float sv = __bfloat162float(g_sh[row * Tt + t]) + __bfloat162float(g_sl[row * Tt + t]);
        const float ev = __bfloat162float(g_eh[row * Tt + t]) + __bfloat162float(g_el[row * Tt + t]);
        a0 += sv * Wsh[0][t * Cc + c];
        a1 += ev * Wsh[1][t * Cc + c];
    }
    g_sWs[gid] = a0;
    g_eWe[gid] = a1;
}
__global__ void wh_proj(const float* __restrict__ wh, const float* __restrict__ linW) {
    __shared__ float tileS[16 * WDd];
    __shared__ float WwS[WDd * Cc];
    const int tid = threadIdx.x;
    const int p0 = blockIdx.x * 16;
#pragma unroll
    for (int l = 0; l < 4; l++) {
        WwS[tid + l * 256]   = linW[2 * Tt * Cc + tid + l * 256];
        tileS[tid + l * 256] = wh[(size_t)p0 * WDd + tid + l * 256];
    }
    __syncthreads();
    const int pl = tid >> 4, c = tid & 15;
    float acc = 0.f;
#pragma unroll
    for (int w = 0; w < WDd; w++)
        acc += tileS[pl * WDd + w] * WwS[w * Cc + c];
    g_whWw[(p0 + pl) * Cc + c] = acc;
}

// ------------------------------- launch
extern "C" void kernel_launch(void* const* d_in, const int* in_sizes, int n_in,
                              void* d_out, int out_size)
{
    const float* fh   = (const float*)d_in[0];
    const float* fv   = (const float*)d_in[1];
    const float* sW   = (const float*)d_in[2];
    const float* sb   = (const float*)d_in[3];
    const float* eW   = (const float*)d_in[4];
    const float* eb   = (const float*)d_in[5];
    const float* U    = (const float*)d_in[6];
    const float* wh   = (const float*)d_in[7];
    const float* linW = (const float*)d_in[8];
    const float* linb = (const float*)d_in[9];
    float* out = (float*)d_out;

    constexpr int SMEM128 = STG * (2 * 128 * 80 + 2 * 128 * 80);   // 122880
    constexpr int SMEM64  = STG * (2 * 64 * 80 + 2 * 128 * 80);    //  92160

    cudaFuncSetAttribute(mma_gemm<64, 0>,  cudaFuncAttributeMaxDynamicSharedMemorySize, SMEM64);
    cudaFuncSetAttribute(mma_gemm<128, 1>, cudaFuncAttributeMaxDynamicSharedMemorySize, SMEM128);
    cudaFuncSetAttribute(mma_gemm<128, 2>, cudaFuncAttributeMaxDynamicSharedMemorySize, SMEM128);

    __nv_bfloat16 *pWth, *pWtl, *pUth, *pUtl;
    cudaGetSymbolAddress((void**)&pWth, g_Wth);
    cudaGetSymbolAddress((void**)&pWtl, g_Wtl);
    cudaGetSymbolAddress((void**)&pUth, g_Uth);
    cudaGetSymbolAddress((void**)&pUtl, g_Utl);

    dim3 tb(32, 8);
    pack_split_x<<<1024, 256>>>(fh, fv);
    transp_split<<<dim3(8, 25),  tb>>>(sW, pWth, pWtl, HF, Tt);
    transp_split<<<dim3(8, 25),  tb>>>(eW, pWth + 256 * HF, pWtl + 256 * HF, HF, Tt);
    transp_split<<<dim3(128, 8), tb>>>(U, pUth, pUtl, Tt, NU);
    wh_proj<<<4096, 256>>>(wh, linW);

    mma_gemm<64, 0><<<dim3(4, 16),     256, SMEM64>>>(sb, eb, nullptr, HF);        // s,e
    proj_se<<<64, 256>>>(linW);
    mma_gemm<128, 1><<<dim3(32, 8),    256, SMEM128>>>(nullptr, nullptr, nullptr, Tt); // sU
    mma_gemm<128, 2><<<dim3(2, 32, 4), 256, SMEM128>>>(linb, nullptr, out, Tt);        // pre
}

// round 6
// speedup vs baseline: 3.1072x; 1.6754x over previous
#include <cuda_runtime.h>
#include <cuda_fp16.h>
#include <cstdint>

#define Hh 768
#define Ff 32
#define Tt 256
#define HF 800
#define BSr 1024
#define NU 4096
#define Cc 16
#define WDd 64
#define Ss 256

// ------------------------------- scratch (device globals)
__device__ __align__(256) __half g_x  [BSr * HF];
__device__ __align__(256) __half g_Wt [512 * HF];
__device__ __align__(256) __half g_Ut [NU * Tt];
__device__ __align__(256) __half g_s16[BSr * Tt];
__device__ __align__(256) __half g_e16[BSr * Tt];
__device__ __align__(256) __half g_sU [BSr * NU];
__device__ float g_sWs[BSr * Cc];
__device__ float g_eWe[BSr * Cc];
__device__ float g_whWw[Ss * Ss * Cc];

// ------------------------------- PTX helpers (baseline sm_100 ISA only)
__device__ __forceinline__ uint32_t smem_u32(const void* p) {
    uint32_t a;
    asm("{ .reg .u64 t; cvta.to.shared.u64 t, %1; cvt.u32.u64 %0, t; }" : "=r"(a) : "l"(p));
    return a;
}
__device__ __forceinline__ void cpa16(uint32_t dst, const void* src) {
    asm volatile("cp.async.cg.shared.global [%0], [%1], 16;" :: "r"(dst), "l"(src));
}
#define CP_COMMIT() asm volatile("cp.async.commit_group;" ::: "memory")
#define CP_WAIT(n)  asm volatile("cp.async.wait_group %0;" :: "n"(n) : "memory")

__device__ __forceinline__ void ldsm4(uint32_t& r0, uint32_t& r1, uint32_t& r2, uint32_t& r3, uint32_t a) {
    asm volatile("ldmatrix.sync.aligned.m8n8.x4.shared.b16 {%0,%1,%2,%3}, [%4];"
                 : "=r"(r0), "=r"(r1), "=r"(r2), "=r"(r3) : "r"(a));
}
__device__ __forceinline__ void mma_f16(float* c, const uint32_t* a, const uint32_t* b) {
    asm volatile("mma.sync.aligned.m16n8k16.row.col.f32.f16.f16.f32 "
                 "{%0,%1,%2,%3},{%4,%5,%6,%7},{%8,%9},{%0,%1,%2,%3};"
                 : "+f"(c[0]), "+f"(c[1]), "+f"(c[2]), "+f"(c[3])
                 : "r"(a[0]), "r"(a[1]), "r"(a[2]), "r"(a[3]), "r"(b[0]), "r"(b[1]));
}
__device__ __forceinline__ uint32_t pkh2(float a, float b) {
    __half2 t = __floats2half2_rn(a, b);
    return *reinterpret_cast<uint32_t*>(&t);
}

constexpr int STG = 3;

// ---------------------------------------------------------------------------
// NT GEMM fp16: D[MT x 128] = A[MT x K] * B[128 x K]^T, f32 accum.
// 8 warps (2m x 4n), warp tile (MT/2) x 32. Single-barrier 3-stage cp.async.
// Epilogues staged through SMEM, fully coalesced.
// EPI: 0 = s/e projection, 1 = sU, 2 = pre (+ fused FFN terms)
// ---------------------------------------------------------------------------
template<int MT, int EPI>
__global__ void __launch_bounds__(256, 2)
mma_gemm(const float* __restrict__ p0, const float* __restrict__ p1,
         float* __restrict__ outp, int K)
{
    constexpr int TA = MT * 80;
    constexpr int TB = 128 * 80;
    constexpr int STAGE = TA + TB;
    constexpr int MI = MT / 32;

    extern __shared__ char sm[];
    const uint32_t smb = smem_u32(sm);
    const int tid = threadIdx.x, lane = tid & 31, w = tid >> 5;
    const int wm = w >> 2, wn = w & 3;

    int m0, n0;
    const __half *A, *B;
    int ld;
    if (EPI == 0) {
        m0 = blockIdx.y * MT; n0 = blockIdx.x * 128; ld = HF;
        A = g_x + (size_t)m0 * HF;
        B = g_Wt + (size_t)n0 * HF;
    } else if (EPI == 1) {
        m0 = blockIdx.y * MT; n0 = blockIdx.x * 128; ld = Tt;
        A = g_s16 + (size_t)m0 * Tt;
        B = g_Ut + (size_t)n0 * Tt;
    } else {
        const int b = blockIdx.z;
        m0 = b * 4096 + blockIdx.y * MT; n0 = blockIdx.x * 128; ld = Tt;
        A = g_sU + (size_t)m0 * Tt;
        B = g_e16 + (size_t)b * Ss * Tt + (size_t)n0 * Tt;
    }

    float acc[MI][4][4] = {};
    const int nk = K / 32;

    auto load_stage = [&](int st, int kb) {
        const uint32_t sb = smb + st * STAGE;
        const int kc = kb * 32;
#pragma unroll
        for (int i = tid; i < MT * 4; i += 256) {
            const int row = i >> 2, ch = i & 3;
            cpa16(sb + row * 80 + ch * 16, A + (size_t)row * ld + kc + ch * 8);
        }
#pragma unroll
        for (int i = tid; i < 512; i += 256) {
            const int row = i >> 2, ch = i & 3;
            cpa16(sb + TA + row * 80 + ch * 16, B + (size_t)row * ld + kc + ch * 8);
        }
    };

    load_stage(0, 0); CP_COMMIT();
    load_stage(1, 1); CP_COMMIT();

    for (int kb = 0; kb < nk; kb++) {
        CP_WAIT(1);
        __syncthreads();
        const int nx = kb + STG - 1;
        if (nx < nk) load_stage(nx % STG, nx);
        CP_COMMIT();

        const uint32_t base = smb + (kb % STG) * STAGE;
        const uint32_t aB = base, bB = base + TA;
#pragma unroll
        for (int ks = 0; ks < 2; ks++) {
            const uint32_t aoff = (uint32_t)(wm * (MT / 2) + (lane & 15)) * 80
                                + ks * 32 + (lane >> 4) * 16;
            uint32_t Af[MI][4];
#pragma unroll
            for (int mi = 0; mi < MI; mi++)
                ldsm4(Af[mi][0], Af[mi][1], Af[mi][2], Af[mi][3], aB + aoff + mi * 16 * 80);
            const uint32_t boff = (uint32_t)(wn * 32 + ((lane >> 4) << 3) + (lane & 7)) * 80
                                + ks * 32 + ((lane >> 3) & 1) * 16;
            uint32_t Bf[8];
            ldsm4(Bf[0], Bf[1], Bf[2], Bf[3], bB + boff);
            ldsm4(Bf[4], Bf[5], Bf[6], Bf[7], bB + boff + 16 * 80);
#pragma unroll
            for (int mi = 0; mi < MI; mi++)
#pragma unroll
                for (int ni = 0; ni < 4; ni++)
                    mma_f16(acc[mi][ni], Af[mi], &Bf[2 * ni]);
        }
    }

    // ---------------- epilogue: stage C in SMEM, coalesced global I/O
    __syncthreads();
    float* Cp = reinterpret_cast<float*>(sm);   // [MT][132]
#pragma unroll
    for (int mi = 0; mi < MI; mi++)
#pragma unroll
        for (int ni = 0; ni < 4; ni++)
#pragma unroll
            for (int r = 0; r < 4; r++) {
                const int ml = wm * (MT / 2) + mi * 16 + (lane >> 2) + ((r >> 1) ? 8 : 0);
                const int nl = wn * 32 + ni * 8 + 2 * (lane & 3) + (r & 1);
                Cp[ml * 132 + nl] = acc[mi][ni][r];
            }
    __syncthreads();

    if (EPI == 0) {
        constexpr int NF4 = MT * 32;
#pragma unroll
        for (int i = tid; i < NF4; i += 256) {
            const int ml = i >> 5, j4 = (i & 31) << 2;
            float4 v = *reinterpret_cast<float4*>(&Cp[ml * 132 + j4]);
            const int n = n0 + j4;
            const float* bias;
            __half* dst;
            int nc;
            if (n < 256) { bias = p0; dst = g_s16; nc = n; }
            else         { bias = p1; dst = g_e16; nc = n - 256; }
            v.x += bias[nc]; v.y += bias[nc + 1]; v.z += bias[nc + 2]; v.w += bias[nc + 3];
            const size_t o = (size_t)(m0 + ml) * Tt + nc;
            *reinterpret_cast<uint2*>(&dst[o]) = make_uint2(pkh2(v.x, v.y), pkh2(v.z, v.w));
        }
    } else if (EPI == 1) {
        constexpr int NF4 = MT * 32;
#pragma unroll
        for (int i = tid; i < NF4; i += 256) {
            const int ml = i >> 5, j4 = (i & 31) << 2;
            float4 v = *reinterpret_cast<float4*>(&Cp[ml * 132 + j4]);
            const size_t o = (size_t)(m0 + ml) * NU + n0 + j4;
            *reinterpret_cast<uint2*>(&g_sU[o]) = make_uint2(pkh2(v.x, v.y), pkh2(v.z, v.w));
        }
    } else {
        const int b = m0 >> 12;
        const int s_base = (m0 >> 4) & 255;
#pragma unroll
        for (int sl_ = 0; sl_ < MT / 16; sl_++) {
            const int s = s_base + sl_;
            float* obase = outp + (((size_t)(b * 256 + s)) * 256 + n0) * 16;
            const float* eweB = g_eWe + (b << 12) + (n0 << 4);
            const float* whB  = g_whWw + (((s << 8) + n0) << 4);
            const float* swB  = g_sWs + m0 + sl_ * 16;
#pragma unroll
            for (int i = tid; i < 512; i += 256) {
                const int e = i >> 2, cq = (i & 3) << 2;
                const int mrow = sl_ * 16 + cq;
                float4 v;
                v.x = Cp[(mrow + 0) * 132 + e];
                v.y = Cp[(mrow + 1) * 132 + e];
                v.z = Cp[(mrow + 2) * 132 + e];
                v.w = Cp[(mrow + 3) * 132 + e];
                float4 ew = *reinterpret_cast<const float4*>(&eweB[e * 16 + cq]);
                float4 wv = *reinterpret_cast<const float4*>(&whB[e * 16 + cq]);
                float4 sw = *reinterpret_cast<const float4*>(&swB[cq]);
                float4 lb = *reinterpret_cast<const float4*>(&p0[cq]);
                v.x += ew.x + wv.x + sw.x + lb.x;
                v.y += ew.y + wv.y + sw.y + lb.y;
                v.z += ew.z + wv.z + sw.z + lb.z;
                v.w += ew.w + wv.w + sw.w + lb.w;
                *reinterpret_cast<float4*>(&obase[e * 16 + cq]) = v;
            }
        }
    }
}

// ------------------------------- prep kernels
__global__ void pack_x(const float* __restrict__ fh, const float* __restrict__ fv) {
    const int row = blockIdx.x;
    for (int k = threadIdx.x; k < HF; k += 256) {
        float v = (k < Hh) ? fh[(size_t)row * Hh + k] : fv[(size_t)row * Ff + k - Hh];
        g_x[(size_t)row * HF + k] = __float2half(v);
    }
}
__global__ void transp_half(const float* __restrict__ src, __half* __restrict__ dst,
                            int R, int C) {
    __shared__ float t[32][33];
    const int bx = blockIdx.x * 32, by = blockIdx.y * 32;
    const int tx = threadIdx.x, ty = threadIdx.y;
#pragma unroll
    for (int j = 0; j < 32; j += 8)
        t[ty + j][tx] = src[(size_t)(by + ty + j) * C + bx + tx];
    __syncthreads();
#pragma unroll
    for (int j = 0; j < 32; j += 8) {
        const int r = by + tx, c = bx + ty + j;
        dst[(size_t)c * R + r] = __float2half(t[tx][ty + j]);
    }
}
__global__ void proj_se(const float* __restrict__ linW) {
    __shared__ float Wsh[2][Tt * Cc];
    const int tid = threadIdx.x;
#pragma unroll
    for (int l = 0; l < 16; l++) {
        Wsh[0][tid + l * 256] = linW[tid + l * 256];
        Wsh[1][tid + l * 256] = linW[Tt * Cc + tid + l * 256];
    }
    __syncthreads();
    const int gid = blockIdx.x * 256 + tid;
    const int row = gid >> 4, c = gid & 15;
    float a0 = 0.f, a1 = 0.f;
#pragma unroll 4
    for (int t = 0; t < Tt; t++) {
        a0 += __half2float(g_s16[row * Tt + t]) * Wsh[0][t * Cc + c];
        a1 += __half2float(g_e16[row * Tt + t]) * Wsh[1][t * Cc + c];
    }
    g_sWs[gid] = a0;
    g_eWe[gid] = a1;
}
__global__ void wh_proj(const float* __restrict__ wh, const float* __restrict__ linW) {
    __shared__ float tileS[16 * WDd];
    __shared__ float WwS[WDd * Cc];
    const int tid = threadIdx.x;
    const int p0 = blockIdx.x * 16;
#pragma unroll
    for (int l = 0; l < 4; l++) {
        WwS[tid + l * 256]   = linW[2 * Tt * Cc + tid + l * 256];
        tileS[tid + l * 256] = wh[(size_t)p0 * WDd + tid + l * 256];
    }
    __syncthreads();
    const int pl = tid >> 4, c = tid & 15;
    float acc = 0.f;
#pragma unroll
    for (int w = 0; w < WDd; w++)
        acc += tileS[pl * WDd + w] * WwS[w * Cc + c];
    g_whWw[(p0 + pl) * Cc + c] = acc;
}

// ------------------------------- launch
extern "C" void kernel_launch(void* const* d_in, const int* in_sizes, int n_in,
                              void* d_out, int out_size)
{
    const float* fh   = (const float*)d_in[0];
    const float* fv   = (const float*)d_in[1];
    const float* sW   = (const float*)d_in[2];
    const float* sb   = (const float*)d_in[3];
    const float* eW   = (const float*)d_in[4];
    const float* eb   = (const float*)d_in[5];
    const float* U    = (const float*)d_in[6];
    const float* wh   = (const float*)d_in[7];
    const float* linW = (const float*)d_in[8];
    const float* linb = (const float*)d_in[9];
    float* out = (float*)d_out;

    // smem = max(pipeline, C-staging)
    constexpr int SMEM128 = 128 * 132 * 4;                      // 67584 (> 3*STAGE=61440)
    constexpr int SMEM64  = STG * (64 * 80 + 128 * 80);         // 46080 (> 64*132*4)

    cudaFuncSetAttribute(mma_gemm<64, 0>,  cudaFuncAttributeMaxDynamicSharedMemorySize, SMEM64);
    cudaFuncSetAttribute(mma_gemm<128, 1>, cudaFuncAttributeMaxDynamicSharedMemorySize, SMEM128);
    cudaFuncSetAttribute(mma_gemm<128, 2>, cudaFuncAttributeMaxDynamicSharedMemorySize, SMEM128);

    __half *pWt, *pUt;
    cudaGetSymbolAddress((void**)&pWt, g_Wt);
    cudaGetSymbolAddress((void**)&pUt, g_Ut);

    dim3 tb(32, 8);
    pack_x<<<1024, 256>>>(fh, fv);
    transp_half<<<dim3(8, 25),  tb>>>(sW, pWt, HF, Tt);
    transp_half<<<dim3(8, 25),  tb>>>(eW, pWt + 256 * HF, HF, Tt);
    transp_half<<<dim3(128, 8), tb>>>(U, pUt, Tt, NU);
    wh_proj<<<4096, 256>>>(wh, linW);

    mma_gemm<64, 0><<<dim3(4, 16),     256, SMEM64>>>(sb, eb, nullptr, HF);            // s,e
    proj_se<<<64, 256>>>(linW);
    mma_gemm<128, 1><<<dim3(32, 8),    256, SMEM128>>>(nullptr, nullptr, nullptr, Tt); // sU
    mma_gemm<128, 2><<<dim3(2, 32, 4), 256, SMEM128>>>(linb, nullptr, out, Tt);        // pre
}

// round 7
// speedup vs baseline: 3.4837x; 1.1212x over previous
#include <cuda_runtime.h>
#include <cuda_fp16.h>
#include <cstdint>

#define Hh 768
#define Ff 32
#define Tt 256
#define HF 800
#define BSr 1024
#define NU 4096
#define Cc 16
#define WDd 64
#define Ss 256

// ------------------------------- scratch (device globals)
__device__ __align__(256) __half g_x   [BSr * HF];      // [1024][800]
__device__ __align__(256) __half g_sW16[HF * Tt];       // [800][256]  K-major
__device__ __align__(256) __half g_eW16[HF * Tt];       // [800][256]  K-major
__device__ __align__(256) __half g_U16 [Tt * NU];       // [256][4096] K-major
__device__ __align__(256) __half g_s16 [BSr * Tt];
__device__ __align__(256) __half g_e16 [BSr * Tt];
__device__ __align__(256) __half g_sU  [BSr * NU];
__device__ float g_sWs[BSr * Cc];
__device__ float g_eWe[BSr * Cc];
__device__ float g_whWw[Ss * Ss * Cc];

// ------------------------------- PTX helpers
__device__ __forceinline__ uint32_t smem_u32(const void* p) {
    uint32_t a;
    asm("{ .reg .u64 t; cvta.to.shared.u64 t, %1; cvt.u32.u64 %0, t; }" : "=r"(a) : "l"(p));
    return a;
}
__device__ __forceinline__ void cpa16(uint32_t dst, const void* src) {
    asm volatile("cp.async.cg.shared.global [%0], [%1], 16;" :: "r"(dst), "l"(src));
}
#define CP_COMMIT() asm volatile("cp.async.commit_group;" ::: "memory")
#define CP_WAIT(n)  asm volatile("cp.async.wait_group %0;" :: "n"(n) : "memory")

__device__ __forceinline__ void ldsm4(uint32_t& r0, uint32_t& r1, uint32_t& r2, uint32_t& r3, uint32_t a) {
    asm volatile("ldmatrix.sync.aligned.m8n8.x4.shared.b16 {%0,%1,%2,%3}, [%4];"
                 : "=r"(r0), "=r"(r1), "=r"(r2), "=r"(r3) : "r"(a));
}
__device__ __forceinline__ void ldsm4t(uint32_t& r0, uint32_t& r1, uint32_t& r2, uint32_t& r3, uint32_t a) {
    asm volatile("ldmatrix.sync.aligned.m8n8.x4.trans.shared.b16 {%0,%1,%2,%3}, [%4];"
                 : "=r"(r0), "=r"(r1), "=r"(r2), "=r"(r3) : "r"(a));
}
__device__ __forceinline__ void mma_f16(float* c, const uint32_t* a, const uint32_t* b) {
    asm volatile("mma.sync.aligned.m16n8k16.row.col.f32.f16.f16.f32 "
                 "{%0,%1,%2,%3},{%4,%5,%6,%7},{%8,%9},{%0,%1,%2,%3};"
                 : "+f"(c[0]), "+f"(c[1]), "+f"(c[2]), "+f"(c[3])
                 : "r"(a[0]), "r"(a[1]), "r"(a[2]), "r"(a[3]), "r"(b[0]), "r"(b[1]));
}
__device__ __forceinline__ uint32_t pkh2(float a, float b) {
    __half2 t = __floats2half2_rn(a, b);
    return *reinterpret_cast<uint32_t*>(&t);
}

constexpr int STG = 3;

// ---------------------------------------------------------------------------
// NT GEMM fp16, f32 accum. D[MT x 128] = A[MT x K] @ B.
// BT=true : B is K-major [K][ldn] in global; staged 32x(128n) rows of 272B,
//           fragments via ldmatrix.trans.
// BT=false: B is n-major [128][K]; staged rows of 80B, ldmatrix non-trans.
// EPI: 0 = s/e projection, 1 = sU, 2 = pre (+ fused FFN terms)
// ---------------------------------------------------------------------------
template<int MT, int EPI, bool BT>
__global__ void __launch_bounds__(256, 2)
mma_gemm(const float* __restrict__ p0, const float* __restrict__ p1,
         float* __restrict__ outp, int K)
{
    constexpr int TA = MT * 80;
    constexpr int TB = BT ? 32 * 272 : 128 * 80;
    constexpr int STAGE = TA + TB;
    constexpr int MI = MT / 32;

    extern __shared__ char sm[];
    const uint32_t smb = smem_u32(sm);
    const int tid = threadIdx.x, lane = tid & 31, w = tid >> 5;
    const int wm = w >> 2, wn = w & 3;

    int m0, n0;
    const __half *A, *Bg;
    int lda, ldn, bn0 = 0;
    if (EPI == 0) {
        m0 = blockIdx.y * MT; n0 = blockIdx.x * 128; lda = HF;
        A = g_x + (size_t)m0 * HF;
        Bg = (n0 < 256) ? g_sW16 : g_eW16;
        bn0 = n0 & 255; ldn = 256;
    } else if (EPI == 1) {
        m0 = blockIdx.y * MT; n0 = blockIdx.x * 128; lda = Tt;
        A = g_s16 + (size_t)m0 * Tt;
        Bg = g_U16; bn0 = n0; ldn = NU;
    } else {
        const int b = blockIdx.z;
        m0 = b * 4096 + blockIdx.y * MT; n0 = blockIdx.x * 128; lda = Tt;
        A = g_sU + (size_t)m0 * Tt;
        Bg = g_e16 + (size_t)b * Ss * Tt + (size_t)n0 * Tt;
        ldn = Tt;
    }

    float acc[MI][4][4] = {};
    const int nk = K / 32;

    auto load_stage = [&](int st, int kb) {
        const uint32_t sb = smb + st * STAGE;
        const int kc = kb * 32;
#pragma unroll
        for (int i = tid; i < MT * 4; i += 256) {
            const int row = i >> 2, ch = i & 3;
            cpa16(sb + row * 80 + ch * 16, A + (size_t)row * lda + kc + ch * 8);
        }
        if (BT) {
#pragma unroll
            for (int i = tid; i < 512; i += 256) {
                const int row = i >> 4, ch = i & 15;   // 32 k-rows x 16 chunks
                cpa16(sb + TA + row * 272 + ch * 16,
                      Bg + (size_t)(kc + row) * ldn + bn0 + ch * 8);
            }
        } else {
#pragma unroll
            for (int i = tid; i < 512; i += 256) {
                const int row = i >> 2, ch = i & 3;    // 128 n-rows x 4 chunks
                cpa16(sb + TA + row * 80 + ch * 16,
                      Bg + (size_t)row * ldn + kc + ch * 8);
            }
        }
    };

    load_stage(0, 0); CP_COMMIT();
    load_stage(1, 1); CP_COMMIT();

    for (int kb = 0; kb < nk; kb++) {
        CP_WAIT(1);
        __syncthreads();
        const int nx = kb + STG - 1;
        if (nx < nk) load_stage(nx % STG, nx);
        CP_COMMIT();

        const uint32_t base = smb + (kb % STG) * STAGE;
        const uint32_t aB = base, bB = base + TA;
#pragma unroll
        for (int ks = 0; ks < 2; ks++) {
            const uint32_t aoff = (uint32_t)(wm * (MT / 2) + (lane & 15)) * 80
                                + ks * 32 + (lane >> 4) * 16;
            uint32_t Af[MI][4];
#pragma unroll
            for (int mi = 0; mi < MI; mi++)
                ldsm4(Af[mi][0], Af[mi][1], Af[mi][2], Af[mi][3], aB + aoff + mi * 16 * 80);
            uint32_t Bf[8];
            if (BT) {
                const uint32_t kk = (uint32_t)(ks * 16 + (lane & 15));
                const uint32_t bo = bB + kk * 272 + wn * 64 + ((lane >> 4) << 4);
                ldsm4t(Bf[0], Bf[1], Bf[2], Bf[3], bo);
                ldsm4t(Bf[4], Bf[5], Bf[6], Bf[7], bo + 32);
            } else {
                const uint32_t boff = (uint32_t)(wn * 32 + ((lane >> 4) << 3) + (lane & 7)) * 80
                                    + ks * 32 + ((lane >> 3) & 1) * 16;
                ldsm4(Bf[0], Bf[1], Bf[2], Bf[3], bB + boff);
                ldsm4(Bf[4], Bf[5], Bf[6], Bf[7], bB + boff + 16 * 80);
            }
#pragma unroll
            for (int mi = 0; mi < MI; mi++)
#pragma unroll
                for (int ni = 0; ni < 4; ni++)
                    mma_f16(acc[mi][ni], Af[mi], &Bf[2 * ni]);
        }
    }

    // ---------------- epilogue: stage C in SMEM, coalesced global I/O
    __syncthreads();
    float* Cp = reinterpret_cast<float*>(sm);   // [MT][132]
#pragma unroll
    for (int mi = 0; mi < MI; mi++)
#pragma unroll
        for (int ni = 0; ni < 4; ni++)
#pragma unroll
            for (int r = 0; r < 4; r++) {
                const int ml = wm * (MT / 2) + mi * 16 + (lane >> 2) + ((r >> 1) ? 8 : 0);
                const int nl = wn * 32 + ni * 8 + 2 * (lane & 3) + (r & 1);
                Cp[ml * 132 + nl] = acc[mi][ni][r];
            }
    __syncthreads();

    if (EPI == 0) {
        const float* bias = (n0 < 256) ? p0 : p1;
        __half* dst = (n0 < 256) ? g_s16 : g_e16;
        const int nc0 = n0 & 255;
        constexpr int NF4 = MT * 32;
#pragma unroll
        for (int i = tid; i < NF4; i += 256) {
            const int ml = i >> 5, j4 = (i & 31) << 2;
            float4 v = *reinterpret_cast<float4*>(&Cp[ml * 132 + j4]);
            const int nc = nc0 + j4;
            v.x += bias[nc]; v.y += bias[nc + 1]; v.z += bias[nc + 2]; v.w += bias[nc + 3];
            const size_t o = (size_t)(m0 + ml) * Tt + nc;
            *reinterpret_cast<uint2*>(&dst[o]) = make_uint2(pkh2(v.x, v.y), pkh2(v.z, v.w));
        }
    } else if (EPI == 1) {
        constexpr int NF4 = MT * 32;
#pragma unroll
        for (int i = tid; i < NF4; i += 256) {
            const int ml = i >> 5, j4 = (i & 31) << 2;
            float4 v = *reinterpret_cast<float4*>(&Cp[ml * 132 + j4]);
            const size_t o = (size_t)(m0 + ml) * NU + n0 + j4;
            *reinterpret_cast<uint2*>(&g_sU[o]) = make_uint2(pkh2(v.x, v.y), pkh2(v.z, v.w));
        }
    } else {
        const int b = m0 >> 12;
        const int s_base = (m0 >> 4) & 255;
#pragma unroll
        for (int sl_ = 0; sl_ < MT / 16; sl_++) {
            const int s = s_base + sl_;
            float* obase = outp + (((size_t)(b * 256 + s)) * 256 + n0) * 16;
            const float* eweB = g_eWe + (b << 12) + (n0 << 4);
            const float* whB  = g_whWw + (((s << 8) + n0) << 4);
            const float* swB  = g_sWs + m0 + sl_ * 16;
#pragma unroll
            for (int i = tid; i < 512; i += 256) {
                const int e = i >> 2, cq = (i & 3) << 2;
                const int mrow = sl_ * 16 + cq;
                float4 v;
                v.x = Cp[(mrow + 0) * 132 + e];
                v.y = Cp[(mrow + 1) * 132 + e];
                v.z = Cp[(mrow + 2) * 132 + e];
                v.w = Cp[(mrow + 3) * 132 + e];
                float4 ew = *reinterpret_cast<const float4*>(&eweB[e * 16 + cq]);
                float4 wv = *reinterpret_cast<const float4*>(&whB[e * 16 + cq]);
                float4 sw = *reinterpret_cast<const float4*>(&swB[cq]);
                float4 lb = *reinterpret_cast<const float4*>(&p0[cq]);
                v.x += ew.x + wv.x + sw.x + lb.x;
                v.y += ew.y + wv.y + sw.y + lb.y;
                v.z += ew.z + wv.z + sw.z + lb.z;
                v.w += ew.w + wv.w + sw.w + lb.w;
                *reinterpret_cast<float4*>(&obase[e * 16 + cq]) = v;
            }
        }
    }
}

// ---------------------------------------------------------------------------
// prep_all: one streaming kernel — converts sW, eW, U to fp16 (same layout,
// K-major) and packs x = [fh|fv] to fp16. All float4 in, half4 (uint2) out.
// ---------------------------------------------------------------------------
__global__ void prep_all(const float* __restrict__ fh, const float* __restrict__ fv,
                         const float* __restrict__ sW, const float* __restrict__ eW,
                         const float* __restrict__ U)
{
    const int i = blockIdx.x * 256 + threadIdx.x;   // float4 index, 0..569343
    float4 v;
    __half* dst;
    size_t o;
    if (i < 51200) {                // sW: 800*256 f32
        v = reinterpret_cast<const float4*>(sW)[i];
        dst = g_sW16; o = (size_t)i * 4;
    } else if (i < 102400) {        // eW
        const int j = i - 51200;
        v = reinterpret_cast<const float4*>(eW)[j];
        dst = g_eW16; o = (size_t)j * 4;
    } else if (i < 364544) {        // U: 256*4096
        const int j = i - 102400;
        v = reinterpret_cast<const float4*>(U)[j];
        dst = g_U16; o = (size_t)j * 4;
    } else {                        // x pack: 1024 rows x 200 float4
        const int j = i - 364544;
        const int row = j / 200, c4 = j % 200;
        if (c4 < 192) v = reinterpret_cast<const float4*>(fh)[row * 192 + c4];
        else          v = reinterpret_cast<const float4*>(fv)[row * 8 + (c4 - 192)];
        dst = g_x; o = (size_t)row * HF + c4 * 4;
    }
    *reinterpret_cast<uint2*>(&dst[o]) = make_uint2(pkh2(v.x, v.y), pkh2(v.z, v.w));
}

__global__ void proj_se(const float* __restrict__ linW) {
    __shared__ float Wsh[2][Tt * Cc];
    const int tid = threadIdx.x;
#pragma unroll
    for (int l = 0; l < 16; l++) {
        Wsh[0][tid + l * 256] = linW[tid + l * 256];
        Wsh[1][tid + l * 256] = linW[Tt * Cc + tid + l * 256];
    }
    __syncthreads();
    const int gid = blockIdx.x * 256 + tid;
    const int row = gid >> 4, c = gid & 15;
    float a0 = 0.f, a1 = 0.f;
#pragma unroll 4
    for (int t = 0; t < Tt; t++) {
        a0 += __half2float(g_s16[row * Tt + t]) * Wsh[0][t * Cc + c];
        a1 += __half2float(g_e16[row * Tt + t]) * Wsh[1][t * Cc + c];
    }
    g_sWs[gid] = a0;
    g_eWe[gid] = a1;
}

__global__ void wh_proj(const float* __restrict__ wh, const float* __restrict__ linW) {
    __shared__ float tileS[16 * WDd];
    __shared__ float WwS[WDd * Cc];
    const int tid = threadIdx.x;
    const int p0 = blockIdx.x * 16;
    {
        float4 a = reinterpret_cast<const float4*>(linW + 2 * Tt * Cc)[tid];
        *reinterpret_cast<float4*>(&WwS[tid * 4]) = a;
        float4 b = reinterpret_cast<const float4*>(wh + (size_t)p0 * WDd)[tid];
        *reinterpret_cast<float4*>(&tileS[tid * 4]) = b;
    }
    __syncthreads();
    const int pl = tid >> 4, c = tid & 15;
    float acc = 0.f;
#pragma unroll
    for (int w = 0; w < WDd; w++)
        acc += tileS[pl * WDd + w] * WwS[w * Cc + c];
    g_whWw[(p0 + pl) * Cc + c] = acc;
}

// ------------------------------- launch
extern "C" void kernel_launch(void* const* d_in, const int* in_sizes, int n_in,
                              void* d_out, int out_size)
{
    const float* fh   = (const float*)d_in[0];
    const float* fv   = (const float*)d_in[1];
    const float* sW   = (const float*)d_in[2];
    const float* sb   = (const float*)d_in[3];
    const float* eW   = (const float*)d_in[4];
    const float* eb   = (const float*)d_in[5];
    const float* U    = (const float*)d_in[6];
    const float* wh   = (const float*)d_in[7];
    const float* linW = (const float*)d_in[8];
    const float* linb = (const float*)d_in[9];
    float* out = (float*)d_out;

    constexpr int SMEM_G0 = STG * (32 * 80 + 32 * 272);      // 33792 > 32*132*4
    constexpr int SMEM_G1 = 128 * 132 * 4;                   // 67584 > 3*(10240+8704)
    constexpr int SMEM_G2 = 128 * 132 * 4;                   // 67584 > 3*(10240+10240)

    cudaFuncSetAttribute(mma_gemm<32, 0, true>,   cudaFuncAttributeMaxDynamicSharedMemorySize, SMEM_G0);
    cudaFuncSetAttribute(mma_gemm<128, 1, true>,  cudaFuncAttributeMaxDynamicSharedMemorySize, SMEM_G1);
    cudaFuncSetAttribute(mma_gemm<128, 2, false>, cudaFuncAttributeMaxDynamicSharedMemorySize, SMEM_G2);

    prep_all<<<2224, 256>>>(fh, fv, sW, eW, U);
    wh_proj<<<4096, 256>>>(wh, linW);

    mma_gemm<32, 0, true><<<dim3(4, 32), 256, SMEM_G0>>>(sb, eb, nullptr, HF);            // s,e
    proj_se<<<64, 256>>>(linW);
    mma_gemm<128, 1, true><<<dim3(32, 8), 256, SMEM_G1>>>(nullptr, nullptr, nullptr, Tt); // sU
    mma_gemm<128, 2, false><<<dim3(2, 32, 4), 256, SMEM_G2>>>(linb, nullptr, out, Tt);    // pre
}

// round 9
// speedup vs baseline: 3.7027x; 1.0629x over previous
#include <cuda_runtime.h>
#include <cuda_fp16.h>
#include <cstdint>

#define Hh 768
#define Ff 32
#define Tt 256
#define HF 800
#define BSr 1024
#define NU 4096
#define Cc 16
#define WDd 64
#define Ss 256

// ------------------------------- scratch (device globals)
__device__ __align__(256) __half g_x   [BSr * HF];      // [1024][800]
__device__ __align__(256) __half g_sW16[HF * Tt];       // [800][256]  K-major
__device__ __align__(256) __half g_eW16[HF * Tt];       // [800][256]  K-major
__device__ __align__(256) __half g_U16 [Tt * NU];       // [256][4096] K-major
__device__ __align__(256) __half g_s16 [BSr * Tt];
__device__ __align__(256) __half g_e16 [BSr * Tt];
__device__ __align__(256) __half g_sU  [BSr * NU];
__device__ float g_sWs[BSr * Cc];
__device__ float g_eWe[BSr * Cc];
__device__ float g_whWw[Ss * Ss * Cc];

// ------------------------------- PTX helpers
__device__ __forceinline__ uint32_t smem_u32(const void* p) {
    uint32_t a;
    asm("{ .reg .u64 t; cvta.to.shared.u64 t, %1; cvt.u32.u64 %0, t; }" : "=r"(a) : "l"(p));
    return a;
}
__device__ __forceinline__ void cpa16(uint32_t dst, const void* src) {
    asm volatile("cp.async.cg.shared.global [%0], [%1], 16;" :: "r"(dst), "l"(src));
}
#define CP_COMMIT() asm volatile("cp.async.commit_group;" ::: "memory")
#define CP_WAIT(n)  asm volatile("cp.async.wait_group %0;" :: "n"(n) : "memory")

__device__ __forceinline__ void ldsm4(uint32_t& r0, uint32_t& r1, uint32_t& r2, uint32_t& r3, uint32_t a) {
    asm volatile("ldmatrix.sync.aligned.m8n8.x4.shared.b16 {%0,%1,%2,%3}, [%4];"
                 : "=r"(r0), "=r"(r1), "=r"(r2), "=r"(r3) : "r"(a));
}
__device__ __forceinline__ void ldsm4t(uint32_t& r0, uint32_t& r1, uint32_t& r2, uint32_t& r3, uint32_t a) {
    asm volatile("ldmatrix.sync.aligned.m8n8.x4.trans.shared.b16 {%0,%1,%2,%3}, [%4];"
                 : "=r"(r0), "=r"(r1), "=r"(r2), "=r"(r3) : "r"(a));
}
__device__ __forceinline__ void mma_f16(float* c, const uint32_t* a, const uint32_t* b) {
    asm volatile("mma.sync.aligned.m16n8k16.row.col.f32.f16.f16.f32 "
                 "{%0,%1,%2,%3},{%4,%5,%6,%7},{%8,%9},{%0,%1,%2,%3};"
                 : "+f"(c[0]), "+f"(c[1]), "+f"(c[2]), "+f"(c[3])
                 : "r"(a[0]), "r"(a[1]), "r"(a[2]), "r"(a[3]), "r"(b[0]), "r"(b[1]));
}
__device__ __forceinline__ uint32_t pkh2(float a, float b) {
    __half2 t = __floats2half2_rn(a, b);
    return *reinterpret_cast<uint32_t*>(&t);
}

constexpr int STG = 3;

// ---------------------------------------------------------------------------
// NT GEMM fp16, f32 accum. D[MT x 128] = A[MT x K] @ B.
// BT=true : B K-major in global, staged 32x(128n) rows of 272B, ldmatrix.trans.
// BT=false: B n-major [128][K], rows of 80B, ldmatrix non-trans.
// EPI: 0 = s/e projection, 1 = sU, 2 = pre (+ fused FFN terms)
// ---------------------------------------------------------------------------
template<int MT, int EPI, bool BT>
__global__ void __launch_bounds__(256, 2)
mma_gemm(const float* __restrict__ p0, const float* __restrict__ p1,
         float* __restrict__ outp, int K)
{
    constexpr int TA = MT * 80;
    constexpr int TB = BT ? 32 * 272 : 128 * 80;
    constexpr int STAGE = TA + TB;
    constexpr int MI = MT / 32;

    extern __shared__ char sm[];
    const uint32_t smb = smem_u32(sm);
    const int tid = threadIdx.x, lane = tid & 31, w = tid >> 5;
    const int wm = w >> 2, wn = w & 3;

    int m0, n0;
    const __half *A, *Bg;
    int lda, ldn, bn0 = 0;
    if (EPI == 0) {
        m0 = blockIdx.y * MT; n0 = blockIdx.x * 128; lda = HF;
        A = g_x + (size_t)m0 * HF;
        Bg = (n0 < 256) ? g_sW16 : g_eW16;
        bn0 = n0 & 255; ldn = 256;
    } else if (EPI == 1) {
        m0 = blockIdx.y * MT; n0 = blockIdx.x * 128; lda = Tt;
        A = g_s16 + (size_t)m0 * Tt;
        Bg = g_U16; bn0 = n0; ldn = NU;
    } else {
        const int b = blockIdx.z;
        m0 = b * 4096 + blockIdx.y * MT; n0 = blockIdx.x * 128; lda = Tt;
        A = g_sU + (size_t)m0 * Tt;
        Bg = g_e16 + (size_t)b * Ss * Tt + (size_t)n0 * Tt;
        ldn = Tt;
    }

    float acc[MI][4][4] = {};
    const int nk = K / 32;

    auto load_stage = [&](int st, int kb) {
        const uint32_t sb = smb + st * STAGE;
        const int kc = kb * 32;
#pragma unroll
        for (int i = tid; i < MT * 4; i += 256) {
            const int row = i >> 2, ch = i & 3;
            cpa16(sb + row * 80 + ch * 16, A + (size_t)row * lda + kc + ch * 8);
        }
        if (BT) {
#pragma unroll
            for (int i = tid; i < 512; i += 256) {
                const int row = i >> 4, ch = i & 15;
                cpa16(sb + TA + row * 272 + ch * 16,
                      Bg + (size_t)(kc + row) * ldn + bn0 + ch * 8);
            }
        } else {
#pragma unroll
            for (int i = tid; i < 512; i += 256) {
                const int row = i >> 2, ch = i & 3;
                cpa16(sb + TA + row * 80 + ch * 16,
                      Bg + (size_t)row * ldn + kc + ch * 8);
            }
        }
    };

    load_stage(0, 0); CP_COMMIT();
    load_stage(1, 1); CP_COMMIT();

    for (int kb = 0; kb < nk; kb++) {
        CP_WAIT(1);
        __syncthreads();
        const int nx = kb + STG - 1;
        if (nx < nk) load_stage(nx % STG, nx);
        CP_COMMIT();

        const uint32_t base = smb + (kb % STG) * STAGE;
        const uint32_t aB = base, bB = base + TA;
#pragma unroll
        for (int ks = 0; ks < 2; ks++) {
            const uint32_t aoff = (uint32_t)(wm * (MT / 2) + (lane & 15)) * 80
                                + ks * 32 + (lane >> 4) * 16;
            uint32_t Af[MI][4];
#pragma unroll
            for (int mi = 0; mi < MI; mi++)
                ldsm4(Af[mi][0], Af[mi][1], Af[mi][2], Af[mi][3], aB + aoff + mi * 16 * 80);
            uint32_t Bf[8];
            if (BT) {
                const uint32_t kk = (uint32_t)(ks * 16 + (lane & 15));
                const uint32_t bo = bB + kk * 272 + wn * 64 + ((lane >> 4) << 4);
                ldsm4t(Bf[0], Bf[1], Bf[2], Bf[3], bo);
                ldsm4t(Bf[4], Bf[5], Bf[6], Bf[7], bo + 32);
            } else {
                const uint32_t boff = (uint32_t)(wn * 32 + ((lane >> 4) << 3) + (lane & 7)) * 80
                                    + ks * 32 + ((lane >> 3) & 1) * 16;
                ldsm4(Bf[0], Bf[1], Bf[2], Bf[3], bB + boff);
                ldsm4(Bf[4], Bf[5], Bf[6], Bf[7], bB + boff + 16 * 80);
            }
#pragma unroll
            for (int mi = 0; mi < MI; mi++)
#pragma unroll
                for (int ni = 0; ni < 4; ni++)
                    mma_f16(acc[mi][ni], Af[mi], &Bf[2 * ni]);
        }
    }

    // ---------------- epilogue: stage C in SMEM, coalesced global I/O
    __syncthreads();
    float* Cp = reinterpret_cast<float*>(sm);   // [MT][132]
#pragma unroll
    for (int mi = 0; mi < MI; mi++)
#pragma unroll
        for (int ni = 0; ni < 4; ni++)
#pragma unroll
            for (int r = 0; r < 4; r++) {
                const int ml = wm * (MT / 2) + mi * 16 + (lane >> 2) + ((r >> 1) ? 8 : 0);
                const int nl = wn * 32 + ni * 8 + 2 * (lane & 3) + (r & 1);
                Cp[ml * 132 + nl] = acc[mi][ni][r];
            }
    __syncthreads();

    if (EPI == 0) {
        const float* bias = (n0 < 256) ? p0 : p1;
        __half* dst = (n0 < 256) ? g_s16 : g_e16;
        const int nc0 = n0 & 255;
        constexpr int NF4 = MT * 32;
#pragma unroll
        for (int i = tid; i < NF4; i += 256) {
            const int ml = i >> 5, j4 = (i & 31) << 2;
            float4 v = *reinterpret_cast<float4*>(&Cp[ml * 132 + j4]);
            const int nc = nc0 + j4;
            v.x += bias[nc]; v.y += bias[nc + 1]; v.z += bias[nc + 2]; v.w += bias[nc + 3];
            const size_t o = (size_t)(m0 + ml) * Tt + nc;
            *reinterpret_cast<uint2*>(&dst[o]) = make_uint2(pkh2(v.x, v.y), pkh2(v.z, v.w));
        }
    } else if (EPI == 1) {
        constexpr int NF4 = MT * 32;
#pragma unroll
        for (int i = tid; i < NF4; i += 256) {
            const int ml = i >> 5, j4 = (i & 31) << 2;
            float4 v = *reinterpret_cast<float4*>(&Cp[ml * 132 + j4]);
            const size_t o = (size_t)(m0 + ml) * NU + n0 + j4;
            *reinterpret_cast<uint2*>(&g_sU[o]) = make_uint2(pkh2(v.x, v.y), pkh2(v.z, v.w));
        }
    } else {
        const int b = m0 >> 12;
        const int s_base = (m0 >> 4) & 255;
#pragma unroll
        for (int sl_ = 0; sl_ < MT / 16; sl_++) {
            const int s = s_base + sl_;
            float* obase = outp + (((size_t)(b * 256 + s)) * 256 + n0) * 16;
            const float* eweB = g_eWe + (b << 12) + (n0 << 4);
            const float* whB  = g_whWw + (((s << 8) + n0) << 4);
            const float* swB  = g_sWs + m0 + sl_ * 16;
#pragma unroll
            for (int i = tid; i < 512; i += 256) {
                const int e = i >> 2, cq = (i & 3) << 2;
                const int mrow = sl_ * 16 + cq;
                float4 v;
                v.x = Cp[(mrow + 0) * 132 + e];
                v.y = Cp[(mrow + 1) * 132 + e];
                v.z = Cp[(mrow + 2) * 132 + e];
                v.w = Cp[(mrow + 3) * 132 + e];
                float4 ew = *reinterpret_cast<const float4*>(&eweB[e * 16 + cq]);
                float4 wv = *reinterpret_cast<const float4*>(&whB[e * 16 + cq]);
                float4 sw = *reinterpret_cast<const float4*>(&swB[cq]);
                float4 lb = *reinterpret_cast<const float4*>(&p0[cq]);
                v.x += ew.x + wv.x + sw.x + lb.x;
                v.y += ew.y + wv.y + sw.y + lb.y;
                v.z += ew.z + wv.z + sw.z + lb.z;
                v.w += ew.w + wv.w + sw.w + lb.w;
                *reinterpret_cast<float4*>(&obase[e * 16 + cq]) = v;
            }
        }
    }
}

// ---------------------------------------------------------------------------
// prep_all: streaming f32->fp16 converts (sW, eW, U, packed x), float4 in.
// ---------------------------------------------------------------------------
__global__ void prep_all(const float* __restrict__ fh, const float* __restrict__ fv,
                         const float* __restrict__ sW, const float* __restrict__ eW,
                         const float* __restrict__ U)
{
    const int i = blockIdx.x * 256 + threadIdx.x;
    float4 v;
    __half* dst;
    size_t o;
    if (i < 51200) {
        v = reinterpret_cast<const float4*>(sW)[i];
        dst = g_sW16; o = (size_t)i * 4;
    } else if (i < 102400) {
        const int j = i - 51200;
        v = reinterpret_cast<const float4*>(eW)[j];
        dst = g_eW16; o = (size_t)j * 4;
    } else if (i < 364544) {
        const int j = i - 102400;
        v = reinterpret_cast<const float4*>(U)[j];
        dst = g_U16; o = (size_t)j * 4;
    } else {
        const int j = i - 364544;
        const int row = j / 200, c4 = j % 200;
        if (c4 < 192) v = reinterpret_cast<const float4*>(fh)[row * 192 + c4];
        else          v = reinterpret_cast<const float4*>(fv)[row * 8 + (c4 - 192)];
        dst = g_x; o = (size_t)row * HF + c4 * 4;
    }
    *reinterpret_cast<uint2*>(&dst[o]) = make_uint2(pkh2(v.x, v.y), pkh2(v.z, v.w));
}

// ---------------------------------------------------------------------------
// proj_se: warp-per-row. 32 lanes = 16 channels x 2 t-halves; half2 loads,
// shfl_xor(16) reduction. 128 blocks x 8 warps.
// ---------------------------------------------------------------------------
__global__ void __launch_bounds__(256, 4) proj_se(const float* __restrict__ linW) {
    __shared__ float Wsh[2][Tt * Cc];   // 2 x 4096 floats = 2 x 1024 float4
    const int tid = threadIdx.x;
#pragma unroll
    for (int l = 0; l < 4; l++) {
        const int i = tid + l * 256;    // float4 idx 0..1023
        float4 a = reinterpret_cast<const float4*>(linW)[i];
        float4 b = reinterpret_cast<const float4*>(linW + Tt * Cc)[i];
        *reinterpret_cast<float4*>(&Wsh[0][i * 4]) = a;
        *reinterpret_cast<float4*>(&Wsh[1][i * 4]) = b;
    }
    __syncthreads();

    const int warp = tid >> 5, lane = tid & 31;
    const int row = blockIdx.x * 8 + warp;
    const int c = lane & 15, th = lane >> 4;
    const __half2* s2 = reinterpret_cast<const __half2*>(g_s16 + (size_t)row * Tt + th * 128);
    const __half2* e2 = reinterpret_cast<const __half2*>(g_e16 + (size_t)row * Tt + th * 128);
    float a0 = 0.f, a1 = 0.f;
#pragma unroll 8
    for (int i = 0; i < 64; i++) {
        const float2 sv = __half22float2(s2[i]);
        const float2 ev = __half22float2(e2[i]);
        const int t = th * 128 + 2 * i;
        a0 += sv.x * Wsh[0][t * Cc + c] + sv.y * Wsh[0][(t + 1) * Cc + c];
        a1 += ev.x * Wsh[1][t * Cc + c] + ev.y * Wsh[1][(t + 1) * Cc + c];
    }
    a0 += __shfl_xor_sync(0xffffffff, a0, 16);
    a1 += __shfl_xor_sync(0xffffffff, a1, 16);
    if (lane < 16) {
        g_sWs[row * Cc + c] = a0;
        g_eWe[row * Cc + c] = a1;
    }
}

__global__ void wh_proj(const float* __restrict__ wh, const float* __restrict__ linW) {
    __shared__ float tileS[16 * WDd];
    __shared__ float WwS[WDd * Cc];
    const int tid = threadIdx.x;
    const int p0 = blockIdx.x * 16;
    {
        float4 a = reinterpret_cast<const float4*>(linW + 2 * Tt * Cc)[tid];
        *reinterpret_cast<float4*>(&WwS[tid * 4]) = a;
        float4 b = reinterpret_cast<const float4*>(wh + (size_t)p0 * WDd)[tid];
        *reinterpret_cast<float4*>(&tileS[tid * 4]) = b;
    }
    __syncthreads();
    const int pl = tid >> 4, c = tid & 15;
    float acc = 0.f;
#pragma unroll
    for (int w = 0; w < WDd; w++)
        acc += tileS[pl * WDd + w] * WwS[w * Cc + c];
    g_whWw[(p0 + pl) * Cc + c] = acc;
}

// ------------------------------- launch
extern "C" void kernel_launch(void* const* d_in, const int* in_sizes, int n_in,
                              void* d_out, int out_size)
{
    const float* fh   = (const float*)d_in[0];
    const float* fv   = (const float*)d_in[1];
    const float* sW   = (const float*)d_in[2];
    const float* sb   = (const float*)d_in[3];
    const float* eW   = (const float*)d_in[4];
    const float* eb   = (const float*)d_in[5];
    const float* U    = (const float*)d_in[6];
    const float* wh   = (const float*)d_in[7];
    const float* linW = (const float*)d_in[8];
    const float* linb = (const float*)d_in[9];
    float* out = (float*)d_out;

    constexpr int SMEM_G0 = STG * (32 * 80 + 32 * 272);
    constexpr int SMEM_G1 = 128 * 132 * 4;
    constexpr int SMEM_G2 = 128 * 132 * 4;

    cudaFuncSetAttribute(mma_gemm<32, 0, true>,   cudaFuncAttributeMaxDynamicSharedMemorySize, SMEM_G0);
    cudaFuncSetAttribute(mma_gemm<128, 1, true>,  cudaFuncAttributeMaxDynamicSharedMemorySize, SMEM_G1);
    cudaFuncSetAttribute(mma_gemm<128, 2, false>, cudaFuncAttributeMaxDynamicSharedMemorySize, SMEM_G2);

    prep_all<<<2224, 256>>>(fh, fv, sW, eW, U);
    wh_proj<<<4096, 256>>>(wh, linW);

    mma_gemm<32, 0, true><<<dim3(4, 32), 256, SMEM_G0>>>(sb, eb, nullptr, HF);            // s,e
    proj_se<<<128, 256>>>(linW);
    mma_gemm<128, 1, true><<<dim3(32, 8), 256, SMEM_G1>>>(nullptr, nullptr, nullptr, Tt); // sU
    mma_gemm<128, 2, false><<<dim3(2, 32, 4), 256, SMEM_G2>>>(linb, nullptr, out, Tt);    // pre
}

// round 10
// speedup vs baseline: 4.2574x; 1.1498x over previous
#include <cuda_runtime.h>
#include <cuda_fp16.h>
#include <cstdint>

#define Hh 768
#define Ff 32
#define Tt 256
#define HF 800
#define BSr 1024
#define NU 4096
#define Cc 16
#define WDd 64
#define Ss 256

// ------------------------------- scratch (device globals)
__device__ __align__(256) __half g_x   [BSr * HF];
__device__ __align__(256) __half g_sW16[HF * Tt];
__device__ __align__(256) __half g_eW16[HF * Tt];
__device__ __align__(256) __half g_U16 [Tt * NU];
__device__ __align__(256) __half g_s16 [BSr * Tt];
__device__ __align__(256) __half g_e16 [BSr * Tt];
__device__ __align__(256) __half g_sU  [BSr * NU];
__device__ float g_prS[2][BSr * Cc];
__device__ float g_prE[2][BSr * Cc];
__device__ float g_whWw[Ss * Ss * Cc];

// ------------------------------- PTX helpers
__device__ __forceinline__ uint32_t smem_u32(const void* p) {
    uint32_t a;
    asm("{ .reg .u64 t; cvta.to.shared.u64 t, %1; cvt.u32.u64 %0, t; }" : "=r"(a) : "l"(p));
    return a;
}
__device__ __forceinline__ void cpa16(uint32_t dst, const void* src) {
    asm volatile("cp.async.cg.shared.global [%0], [%1], 16;" :: "r"(dst), "l"(src));
}
#define CP_COMMIT() asm volatile("cp.async.commit_group;" ::: "memory")
#define CP_WAIT(n)  asm volatile("cp.async.wait_group %0;" :: "n"(n) : "memory")

__device__ __forceinline__ void ldsm4(uint32_t& r0, uint32_t& r1, uint32_t& r2, uint32_t& r3, uint32_t a) {
    asm volatile("ldmatrix.sync.aligned.m8n8.x4.shared.b16 {%0,%1,%2,%3}, [%4];"
                 : "=r"(r0), "=r"(r1), "=r"(r2), "=r"(r3) : "r"(a));
}
__device__ __forceinline__ void ldsm4t(uint32_t& r0, uint32_t& r1, uint32_t& r2, uint32_t& r3, uint32_t a) {
    asm volatile("ldmatrix.sync.aligned.m8n8.x4.trans.shared.b16 {%0,%1,%2,%3}, [%4];"
                 : "=r"(r0), "=r"(r1), "=r"(r2), "=r"(r3) : "r"(a));
}
__device__ __forceinline__ void mma_f16(float* c, const uint32_t* a, const uint32_t* b) {
    asm volatile("mma.sync.aligned.m16n8k16.row.col.f32.f16.f16.f32 "
                 "{%0,%1,%2,%3},{%4,%5,%6,%7},{%8,%9},{%0,%1,%2,%3};"
                 : "+f"(c[0]), "+f"(c[1]), "+f"(c[2]), "+f"(c[3])
                 : "r"(a[0]), "r"(a[1]), "r"(a[2]), "r"(a[3]), "r"(b[0]), "r"(b[1]));
}
__device__ __forceinline__ uint32_t pkh2(float a, float b) {
    __half2 t = __floats2half2_rn(a, b);
    return *reinterpret_cast<uint32_t*>(&t);
}

constexpr int STG = 3;

// ---------------------------------------------------------------------------
// NT GEMM fp16, f32 accum. D[MT x 128] = A[MT x K] @ B.
// EPI: 0 = s/e projection (+ fused partial s@Ws / e@We; linW passed via outp),
//      1 = sU, 2 = pre (+ fused FFN terms)
// ---------------------------------------------------------------------------
template<int MT, int EPI, bool BT>
__global__ void __launch_bounds__(256, 2)
mma_gemm(const float* __restrict__ p0, const float* __restrict__ p1,
         float* __restrict__ outp, int K)
{
    constexpr int TA = MT * 80;
    constexpr int TB = BT ? 32 * 272 : 128 * 80;
    constexpr int STAGE = TA + TB;
    constexpr int MI = MT / 32;

    extern __shared__ char sm[];
    const uint32_t smb = smem_u32(sm);
    const int tid = threadIdx.x, lane = tid & 31, w = tid >> 5;
    const int wm = w >> 2, wn = w & 3;

    int m0, n0;
    const __half *A, *Bg;
    int lda, ldn, bn0 = 0;
    if (EPI == 0) {
        m0 = blockIdx.y * MT; n0 = blockIdx.x * 128; lda = HF;
        A = g_x + (size_t)m0 * HF;
        Bg = (n0 < 256) ? g_sW16 : g_eW16;
        bn0 = n0 & 255; ldn = 256;
    } else if (EPI == 1) {
        m0 = blockIdx.y * MT; n0 = blockIdx.x * 128; lda = Tt;
        A = g_s16 + (size_t)m0 * Tt;
        Bg = g_U16; bn0 = n0; ldn = NU;
    } else {
        const int b = blockIdx.z;
        m0 = b * 4096 + blockIdx.y * MT; n0 = blockIdx.x * 128; lda = Tt;
        A = g_sU + (size_t)m0 * Tt;
        Bg = g_e16 + (size_t)b * Ss * Tt + (size_t)n0 * Tt;
        ldn = Tt;
    }

    float acc[MI][4][4] = {};
    const int nk = K / 32;

    auto load_stage = [&](int st, int kb) {
        const uint32_t sb = smb + st * STAGE;
        const int kc = kb * 32;
#pragma unroll
        for (int i = tid; i < MT * 4; i += 256) {
            const int row = i >> 2, ch = i & 3;
            cpa16(sb + row * 80 + ch * 16, A + (size_t)row * lda + kc + ch * 8);
        }
        if (BT) {
#pragma unroll
            for (int i = tid; i < 512; i += 256) {
                const int row = i >> 4, ch = i & 15;
                cpa16(sb + TA + row * 272 + ch * 16,
                      Bg + (size_t)(kc + row) * ldn + bn0 + ch * 8);
            }
        } else {
#pragma unroll
            for (int i = tid; i < 512; i += 256) {
                const int row = i >> 2, ch = i & 3;
                cpa16(sb + TA + row * 80 + ch * 16,
                      Bg + (size_t)row * ldn + kc + ch * 8);
            }
        }
    };

    load_stage(0, 0); CP_COMMIT();
    load_stage(1, 1); CP_COMMIT();

    for (int kb = 0; kb < nk; kb++) {
        CP_WAIT(1);
        __syncthreads();
        const int nx = kb + STG - 1;
        if (nx < nk) load_stage(nx % STG, nx);
        CP_COMMIT();

        const uint32_t base = smb + (kb % STG) * STAGE;
        const uint32_t aB = base, bB = base + TA;
#pragma unroll
        for (int ks = 0; ks < 2; ks++) {
            const uint32_t aoff = (uint32_t)(wm * (MT / 2) + (lane & 15)) * 80
                                + ks * 32 + (lane >> 4) * 16;
            uint32_t Af[MI][4];
#pragma unroll
            for (int mi = 0; mi < MI; mi++)
                ldsm4(Af[mi][0], Af[mi][1], Af[mi][2], Af[mi][3], aB + aoff + mi * 16 * 80);
            uint32_t Bf[8];
            if (BT) {
                const uint32_t kk = (uint32_t)(ks * 16 + (lane & 15));
                const uint32_t bo = bB + kk * 272 + wn * 64 + ((lane >> 4) << 4);
                ldsm4t(Bf[0], Bf[1], Bf[2], Bf[3], bo);
                ldsm4t(Bf[4], Bf[5], Bf[6], Bf[7], bo + 32);
            } else {
                const uint32_t boff = (uint32_t)(wn * 32 + ((lane >> 4) << 3) + (lane & 7)) * 80
                                    + ks * 32 + ((lane >> 3) & 1) * 16;
                ldsm4(Bf[0], Bf[1], Bf[2], Bf[3], bB + boff);
                ldsm4(Bf[4], Bf[5], Bf[6], Bf[7], bB + boff + 16 * 80);
            }
#pragma unroll
            for (int mi = 0; mi < MI; mi++)
#pragma unroll
                for (int ni = 0; ni < 4; ni++)
                    mma_f16(acc[mi][ni], Af[mi], &Bf[2 * ni]);
        }
    }

    __syncthreads();
    float* Cp = reinterpret_cast<float*>(sm);   // [MT][132]
#pragma unroll
    for (int mi = 0; mi < MI; mi++)
#pragma unroll
        for (int ni = 0; ni < 4; ni++)
#pragma unroll
            for (int r = 0; r < 4; r++) {
                const int ml = wm * (MT / 2) + mi * 16 + (lane >> 2) + ((r >> 1) ? 8 : 0);
                const int nl = wn * 32 + ni * 8 + 2 * (lane & 3) + (r & 1);
                Cp[ml * 132 + nl] = acc[mi][ni][r];
            }
    __syncthreads();

    if (EPI == 0) {
        const float* bias = (n0 < 256) ? p0 : p1;
        const float* linW = outp;                    // smuggled
        __half* dst = (n0 < 256) ? g_s16 : g_e16;
        const int nc0 = n0 & 255;
        constexpr int NF4 = MT * 32;
#pragma unroll
        for (int i = tid; i < NF4; i += 256) {
            const int ml = i >> 5, j4 = (i & 31) << 2;
            float4 v = *reinterpret_cast<float4*>(&Cp[ml * 132 + j4]);
            const int nc = nc0 + j4;
            v.x += bias[nc]; v.y += bias[nc + 1]; v.z += bias[nc + 2]; v.w += bias[nc + 3];
            *reinterpret_cast<float4*>(&Cp[ml * 132 + j4]) = v;
            const size_t o = (size_t)(m0 + ml) * Tt + nc;
            *reinterpret_cast<uint2*>(&dst[o]) = make_uint2(pkh2(v.x, v.y), pkh2(v.z, v.w));
        }
        float* Wp = Cp + MT * 132;                   // 128x16 f32 = 8 KB
#pragma unroll
        for (int i = tid; i < 512; i += 256)
            *reinterpret_cast<float4*>(&Wp[i * 4]) =
                reinterpret_cast<const float4*>(linW)[n0 * 4 + i];
        __syncthreads();
        float* dpr = (n0 < 256) ? g_prS[(n0 >> 7) & 1] : g_prE[(n0 >> 7) & 1];
        const int c = lane & 15, th = lane >> 4;
        float ap[4] = {};
#pragma unroll 8
        for (int j = 0; j < 64; j++) {
            const int t = th * 64 + j;
            const float wv = Wp[t * Cc + c];
#pragma unroll
            for (int r = 0; r < 4; r++)
                ap[r] += Cp[(w * 4 + r) * 132 + t] * wv;
        }
#pragma unroll
        for (int r = 0; r < 4; r++)
            ap[r] += __shfl_xor_sync(0xffffffff, ap[r], 16);
        if (lane < 16) {
#pragma unroll
            for (int r = 0; r < 4; r++)
                dpr[(m0 + w * 4 + r) * Cc + c] = ap[r];
        }
    } else if (EPI == 1) {
        constexpr int NF4 = MT * 32;
#pragma unroll
        for (int i = tid; i < NF4; i += 256) {
            const int ml = i >> 5, j4 = (i & 31) << 2;
            float4 v = *reinterpret_cast<float4*>(&Cp[ml * 132 + j4]);
            const size_t o = (size_t)(m0 + ml) * NU + n0 + j4;
            *reinterpret_cast<uint2*>(&g_sU[o]) = make_uint2(pkh2(v.x, v.y), pkh2(v.z, v.w));
        }
    } else {
        const int b = m0 >> 12;
        const int s_base = (m0 >> 4) & 255;
#pragma unroll
        for (int sl_ = 0; sl_ < MT / 16; sl_++) {
            const int s = s_base + sl_;
            float* obase = outp + (((size_t)(b * 256 + s)) * 256 + n0) * 16;
            const int eoff = (b << 12) + (n0 << 4);
            const float* whB = g_whWw + (((s << 8) + n0) << 4);
            const int swoff = m0 + sl_ * 16;
#pragma unroll
            for (int i = tid; i < 512; i += 256) {
                const int e = i >> 2, cq = (i & 3) << 2;
                const int mrow = sl_ * 16 + cq;
                float4 v;
                v.x = Cp[(mrow + 0) * 132 + e];
                v.y = Cp[(mrow + 1) * 132 + e];
                v.z = Cp[(mrow + 2) * 132 + e];
                v.w = Cp[(mrow + 3) * 132 + e];
                float4 ew0 = *reinterpret_cast<const float4*>(&g_prE[0][eoff + e * 16 + cq]);
                float4 ew1 = *reinterpret_cast<const float4*>(&g_prE[1][eoff + e * 16 + cq]);
                float4 wv  = *reinterpret_cast<const float4*>(&whB[e * 16 + cq]);
                float4 sw0 = *reinterpret_cast<const float4*>(&g_prS[0][swoff + cq]);
                float4 sw1 = *reinterpret_cast<const float4*>(&g_prS[1][swoff + cq]);
                float4 lb  = *reinterpret_cast<const float4*>(&p0[cq]);
                v.x += ew0.x + ew1.x + wv.x + sw0.x + sw1.x + lb.x;
                v.y += ew0.y + ew1.y + wv.y + sw0.y + sw1.y + lb.y;
                v.z += ew0.z + ew1.z + wv.z + sw0.z + sw1.z + lb.z;
                v.w += ew0.w + ew1.w + wv.w + sw0.w + sw1.w + lb.w;
                *reinterpret_cast<float4*>(&obase[e * 16 + cq]) = v;
            }
        }
    }
}

// ---------------------------------------------------------------------------
__global__ void prep_all(const float* __restrict__ fh, const float* __restrict__ fv,
                         const float* __restrict__ sW, const float* __restrict__ eW,
                         const float* __restrict__ U)
{
    const int i = blockIdx.x * 256 + threadIdx.x;
    float4 v;
    __half* dst;
    size_t o;
    if (i < 51200) {
        v = reinterpret_cast<const float4*>(sW)[i];
        dst = g_sW16; o = (size_t)i * 4;
    } else if (i < 102400) {
        const int j = i - 51200;
        v = reinterpret_cast<const float4*>(eW)[j];
        dst = g_eW16; o = (size_t)j * 4;
    } else if (i < 364544) {
        const int j = i - 102400;
        v = reinterpret_cast<const float4*>(U)[j];
        dst = g_U16; o = (size_t)j * 4;
    } else {
        const int j = i - 364544;
        const int row = j / 200, c4 = j % 200;
        if (c4 < 192) v = reinterpret_cast<const float4*>(fh)[row * 192 + c4];
        else          v = reinterpret_cast<const float4*>(fv)[row * 8 + (c4 - 192)];
        dst = g_x; o = (size_t)row * HF + c4 * 4;
    }
    *reinterpret_cast<uint2*>(&dst[o]) = make_uint2(pkh2(v.x, v.y), pkh2(v.z, v.w));
}

// ---------------------------------------------------------------------------
// wh_proj: 1024 blocks x 64 p-rows, 4 independent float4 loads/thread (MLP 4).
// ---------------------------------------------------------------------------
__global__ void wh_proj(const float* __restrict__ wh, const float* __restrict__ linW) {
    __shared__ float tileS[64 * WDd];
    __shared__ float WwS[WDd * Cc];
    const int tid = threadIdx.x;
    const int p0 = blockIdx.x * 64;
    {
        float4 a = reinterpret_cast<const float4*>(linW + 2 * Tt * Cc)[tid];
        *reinterpret_cast<float4*>(&WwS[tid * 4]) = a;
        const float4* src = reinterpret_cast<const float4*>(wh + (size_t)p0 * WDd);
#pragma unroll
        for (int l = 0; l < 4; l++) {
            float4 b = src[tid + l * 256];
            *reinterpret_cast<float4*>(&tileS[(tid + l * 256) * 4]) = b;
        }
    }
    __syncthreads();
    const int c = tid & 15, pl0 = (tid >> 4) * 4;
#pragma unroll
    for (int r = 0; r < 4; r++) {
        const int pl = pl0 + r;
        float acc = 0.f;
#pragma unroll
        for (int w = 0; w < WDd; w++)
            acc += tileS[pl * WDd + w] * WwS[w * Cc + c];
        g_whWw[(p0 + pl) * Cc + c] = acc;
    }
}

// ------------------------------- launch
extern "C" void kernel_launch(void* const* d_in, const int* in_sizes, int n_in,
                              void* d_out, int out_size)
{
    const float* fh   = (const float*)d_in[0];
    const float* fv   = (const float*)d_in[1];
    const float* sW   = (const float*)d_in[2];
    const float* sb   = (const float*)d_in[3];
    const float* eW   = (const float*)d_in[4];
    const float* eb   = (const float*)d_in[5];
    const float* U    = (const float*)d_in[6];
    const float* wh   = (const float*)d_in[7];
    const float* linW = (const float*)d_in[8];
    const float* linb = (const float*)d_in[9];
    float* out = (float*)d_out;

    constexpr int SMEM_G0 = STG * (32 * 80 + 32 * 272);   // 33792 >= 16896 + 8192
    constexpr int SMEM_G1 = 128 * 132 * 4;
    constexpr int SMEM_G2 = 128 * 132 * 4;

    cudaFuncSetAttribute(mma_gemm<32, 0, true>,   cudaFuncAttributeMaxDynamicSharedMemorySize, SMEM_G0);
    cudaFuncSetAttribute(mma_gemm<128, 1, true>,  cudaFuncAttributeMaxDynamicSharedMemorySize, SMEM_G1);
    cudaFuncSetAttribute(mma_gemm<128, 2, false>, cudaFuncAttributeMaxDynamicSharedMemorySize, SMEM_G2);

    prep_all<<<2224, 256>>>(fh, fv, sW, eW, U);
    wh_proj<<<1024, 256>>>(wh, linW);

    mma_gemm<32, 0, true><<<dim3(4, 32), 256, SMEM_G0>>>(sb, eb, (float*)linW, HF);       // s,e + proj
    mma_gemm<128, 1, true><<<dim3(32, 8), 256, SMEM_G1>>>(nullptr, nullptr, nullptr, Tt); // sU
    mma_gemm<128, 2, false><<<dim3(2, 32, 4), 256, SMEM_G2>>>(linb, nullptr, out, Tt);    // pre
}

// round 11
// speedup vs baseline: 4.2598x; 1.0006x over previous
#include <cuda_runtime.h>
#include <cuda_fp16.h>
#include <cstdint>

#define Hh 768
#define Ff 32
#define Tt 256
#define HF 800
#define BSr 1024
#define NU 4096
#define Cc 16
#define WDd 64
#define Ss 256

// ------------------------------- scratch (device globals)
__device__ __align__(256) __half g_x   [BSr * HF];
__device__ __align__(256) __half g_sW16[HF * Tt];
__device__ __align__(256) __half g_eW16[HF * Tt];
__device__ __align__(256) __half g_U16 [Tt * NU];
__device__ __align__(256) __half g_s16 [BSr * Tt];
__device__ __align__(256) __half g_e16 [BSr * Tt];
__device__ __align__(256) __half g_sU  [BSr * NU];
__device__ float g_prS[2][BSr * Cc];
__device__ float g_prE[2][BSr * Cc];
__device__ float g_whWw[Ss * Ss * Cc];

// ------------------------------- PTX helpers
__device__ __forceinline__ uint32_t smem_u32(const void* p) {
    uint32_t a;
    asm("{ .reg .u64 t; cvta.to.shared.u64 t, %1; cvt.u32.u64 %0, t; }" : "=r"(a) : "l"(p));
    return a;
}
__device__ __forceinline__ void cpa16(uint32_t dst, const void* src) {
    asm volatile("cp.async.cg.shared.global [%0], [%1], 16;" :: "r"(dst), "l"(src));
}
#define CP_COMMIT() asm volatile("cp.async.commit_group;" ::: "memory")
#define CP_WAIT(n)  asm volatile("cp.async.wait_group %0;" :: "n"(n) : "memory")

__device__ __forceinline__ void ldsm4(uint32_t& r0, uint32_t& r1, uint32_t& r2, uint32_t& r3, uint32_t a) {
    asm volatile("ldmatrix.sync.aligned.m8n8.x4.shared.b16 {%0,%1,%2,%3}, [%4];"
                 : "=r"(r0), "=r"(r1), "=r"(r2), "=r"(r3) : "r"(a));
}
__device__ __forceinline__ void ldsm4t(uint32_t& r0, uint32_t& r1, uint32_t& r2, uint32_t& r3, uint32_t a) {
    asm volatile("ldmatrix.sync.aligned.m8n8.x4.trans.shared.b16 {%0,%1,%2,%3}, [%4];"
                 : "=r"(r0), "=r"(r1), "=r"(r2), "=r"(r3) : "r"(a));
}
__device__ __forceinline__ void mma_f16(float* c, const uint32_t* a, const uint32_t* b) {
    asm volatile("mma.sync.aligned.m16n8k16.row.col.f32.f16.f16.f32 "
                 "{%0,%1,%2,%3},{%4,%5,%6,%7},{%8,%9},{%0,%1,%2,%3};"
                 : "+f"(c[0]), "+f"(c[1]), "+f"(c[2]), "+f"(c[3])
                 : "r"(a[0]), "r"(a[1]), "r"(a[2]), "r"(a[3]), "r"(b[0]), "r"(b[1]));
}
__device__ __forceinline__ uint32_t pkh2(float a, float b) {
    __half2 t = __floats2half2_rn(a, b);
    return *reinterpret_cast<uint32_t*>(&t);
}

constexpr int STG = 5;    // deep pipeline: ~4 iterations of load-latency coverage

// ---------------------------------------------------------------------------
// NT GEMM fp16, f32 accum. D[MT x 128] = A[MT x K] @ B.
// EPI: 0 = s/e projection (+ fused partial s@Ws / e@We; linW via outp),
//      1 = sU, 2 = pre (+ fused FFN terms)
// ---------------------------------------------------------------------------
template<int MT, int EPI, bool BT>
__global__ void __launch_bounds__(256, 2)
mma_gemm(const float* __restrict__ p0, const float* __restrict__ p1,
         float* __restrict__ outp, int K)
{
    constexpr int TA = MT * 80;
    constexpr int TB = BT ? 32 * 272 : 128 * 80;
    constexpr int STAGE = TA + TB;
    constexpr int MI = MT / 32;

    extern __shared__ char sm[];
    const uint32_t smb = smem_u32(sm);
    const int tid = threadIdx.x, lane = tid & 31, w = tid >> 5;
    const int wm = w >> 2, wn = w & 3;

    int m0, n0;
    const __half *A, *Bg;
    int lda, ldn, bn0 = 0;
    if (EPI == 0) {
        m0 = blockIdx.y * MT; n0 = blockIdx.x * 128; lda = HF;
        A = g_x + (size_t)m0 * HF;
        Bg = (n0 < 256) ? g_sW16 : g_eW16;
        bn0 = n0 & 255; ldn = 256;
    } else if (EPI == 1) {
        m0 = blockIdx.y * MT; n0 = blockIdx.x * 128; lda = Tt;
        A = g_s16 + (size_t)m0 * Tt;
        Bg = g_U16; bn0 = n0; ldn = NU;
    } else {
        const int b = blockIdx.z;
        m0 = b * 4096 + blockIdx.y * MT; n0 = blockIdx.x * 128; lda = Tt;
        A = g_sU + (size_t)m0 * Tt;
        Bg = g_e16 + (size_t)b * Ss * Tt + (size_t)n0 * Tt;
        ldn = Tt;
    }

    float acc[MI][4][4] = {};
    const int nk = K / 32;

    auto load_stage = [&](int st, int kb) {
        const uint32_t sb = smb + st * STAGE;
        const int kc = kb * 32;
#pragma unroll
        for (int i = tid; i < MT * 4; i += 256) {
            const int row = i >> 2, ch = i & 3;
            cpa16(sb + row * 80 + ch * 16, A + (size_t)row * lda + kc + ch * 8);
        }
        if (BT) {
#pragma unroll
            for (int i = tid; i < 512; i += 256) {
                const int row = i >> 4, ch = i & 15;
                cpa16(sb + TA + row * 272 + ch * 16,
                      Bg + (size_t)(kc + row) * ldn + bn0 + ch * 8);
            }
        } else {
#pragma unroll
            for (int i = tid; i < 512; i += 256) {
                const int row = i >> 2, ch = i & 3;
                cpa16(sb + TA + row * 80 + ch * 16,
                      Bg + (size_t)row * ldn + kc + ch * 8);
            }
        }
    };

#pragma unroll
    for (int s = 0; s < STG - 1; s++) {
        if (s < nk) load_stage(s, s);
        CP_COMMIT();
    }

    for (int kb = 0; kb < nk; kb++) {
        CP_WAIT(STG - 2);
        __syncthreads();
        const int nx = kb + STG - 1;
        if (nx < nk) load_stage(nx % STG, nx);
        CP_COMMIT();

        const uint32_t base = smb + (kb % STG) * STAGE;
        const uint32_t aB = base, bB = base + TA;
#pragma unroll
        for (int ks = 0; ks < 2; ks++) {
            const uint32_t aoff = (uint32_t)(wm * (MT / 2) + (lane & 15)) * 80
                                + ks * 32 + (lane >> 4) * 16;
            uint32_t Af[MI][4];
#pragma unroll
            for (int mi = 0; mi < MI; mi++)
                ldsm4(Af[mi][0], Af[mi][1], Af[mi][2], Af[mi][3], aB + aoff + mi * 16 * 80);
            uint32_t Bf[8];
            if (BT) {
                const uint32_t kk = (uint32_t)(ks * 16 + (lane & 15));
                const uint32_t bo = bB + kk * 272 + wn * 64 + ((lane >> 4) << 4);
                ldsm4t(Bf[0], Bf[1], Bf[2], Bf[3], bo);
                ldsm4t(Bf[4], Bf[5], Bf[6], Bf[7], bo + 32);
            } else {
                const uint32_t boff = (uint32_t)(wn * 32 + ((lane >> 4) << 3) + (lane & 7)) * 80
                                    + ks * 32 + ((lane >> 3) & 1) * 16;
                ldsm4(Bf[0], Bf[1], Bf[2], Bf[3], bB + boff);
                ldsm4(Bf[4], Bf[5], Bf[6], Bf[7], bB + boff + 16 * 80);
            }
#pragma unroll
            for (int mi = 0; mi < MI; mi++)
#pragma unroll
                for (int ni = 0; ni < 4; ni++)
                    mma_f16(acc[mi][ni], Af[mi], &Bf[2 * ni]);
        }
    }

    __syncthreads();
    float* Cp = reinterpret_cast<float*>(sm);   // [MT][132]
#pragma unroll
    for (int mi = 0; mi < MI; mi++)
#pragma unroll
        for (int ni = 0; ni < 4; ni++)
#pragma unroll
            for (int r = 0; r < 4; r++) {
                const int ml = wm * (MT / 2) + mi * 16 + (lane >> 2) + ((r >> 1) ? 8 : 0);
                const int nl = wn * 32 + ni * 8 + 2 * (lane & 3) + (r & 1);
                Cp[ml * 132 + nl] = acc[mi][ni][r];
            }
    __syncthreads();

    if (EPI == 0) {
        const float* bias = (n0 < 256) ? p0 : p1;
        const float* linW = outp;                    // smuggled
        __half* dst = (n0 < 256) ? g_s16 : g_e16;
        const int nc0 = n0 & 255;
        constexpr int NF4 = MT * 32;
#pragma unroll
        for (int i = tid; i < NF4; i += 256) {
            const int ml = i >> 5, j4 = (i & 31) << 2;
            float4 v = *reinterpret_cast<float4*>(&Cp[ml * 132 + j4]);
            const int nc = nc0 + j4;
            v.x += bias[nc]; v.y += bias[nc + 1]; v.z += bias[nc + 2]; v.w += bias[nc + 3];
            *reinterpret_cast<float4*>(&Cp[ml * 132 + j4]) = v;
            const size_t o = (size_t)(m0 + ml) * Tt + nc;
            *reinterpret_cast<uint2*>(&dst[o]) = make_uint2(pkh2(v.x, v.y), pkh2(v.z, v.w));
        }
        float* Wp = Cp + MT * 132;                   // 128x16 f32 = 8 KB
#pragma unroll
        for (int i = tid; i < 512; i += 256)
            *reinterpret_cast<float4*>(&Wp[i * 4]) =
                reinterpret_cast<const float4*>(linW)[n0 * 4 + i];
        __syncthreads();
        float* dpr = (n0 < 256) ? g_prS[(n0 >> 7) & 1] : g_prE[(n0 >> 7) & 1];
        const int c = lane & 15, th = lane >> 4;
        float ap[4] = {};
#pragma unroll 8
        for (int j = 0; j < 64; j++) {
            const int t = th * 64 + j;
            const float wv = Wp[t * Cc + c];
#pragma unroll
            for (int r = 0; r < 4; r++)
                ap[r] += Cp[(w * 4 + r) * 132 + t] * wv;
        }
#pragma unroll
        for (int r = 0; r < 4; r++)
            ap[r] += __shfl_xor_sync(0xffffffff, ap[r], 16);
        if (lane < 16) {
#pragma unroll
            for (int r = 0; r < 4; r++)
                dpr[(m0 + w * 4 + r) * Cc + c] = ap[r];
        }
    } else if (EPI == 1) {
        constexpr int NF4 = MT * 32;
#pragma unroll
        for (int i = tid; i < NF4; i += 256) {
            const int ml = i >> 5, j4 = (i & 31) << 2;
            float4 v = *reinterpret_cast<float4*>(&Cp[ml * 132 + j4]);
            const size_t o = (size_t)(m0 + ml) * NU + n0 + j4;
            *reinterpret_cast<uint2*>(&g_sU[o]) = make_uint2(pkh2(v.x, v.y), pkh2(v.z, v.w));
        }
    } else {
        const int b = m0 >> 12;
        const int s_base = (m0 >> 4) & 255;
#pragma unroll
        for (int sl_ = 0; sl_ < MT / 16; sl_++) {
            const int s = s_base + sl_;
            float* obase = outp + (((size_t)(b * 256 + s)) * 256 + n0) * 16;
            const int eoff = (b << 12) + (n0 << 4);
            const float* whB = g_whWw + (((s << 8) + n0) << 4);
            const int swoff = m0 + sl_ * 16;
#pragma unroll
            for (int i = tid; i < 512; i += 256) {
                const int e = i >> 2, cq = (i & 3) << 2;
                const int mrow = sl_ * 16 + cq;
                float4 v;
                v.x = Cp[(mrow + 0) * 132 + e];
                v.y = Cp[(mrow + 1) * 132 + e];
                v.z = Cp[(mrow + 2) * 132 + e];
                v.w = Cp[(mrow + 3) * 132 + e];
                float4 ew0 = *reinterpret_cast<const float4*>(&g_prE[0][eoff + e * 16 + cq]);
                float4 ew1 = *reinterpret_cast<const float4*>(&g_prE[1][eoff + e * 16 + cq]);
                float4 wv  = *reinterpret_cast<const float4*>(&whB[e * 16 + cq]);
                float4 sw0 = *reinterpret_cast<const float4*>(&g_prS[0][swoff + cq]);
                float4 sw1 = *reinterpret_cast<const float4*>(&g_prS[1][swoff + cq]);
                float4 lb  = *reinterpret_cast<const float4*>(&p0[cq]);
                v.x += ew0.x + ew1.x + wv.x + sw0.x + sw1.x + lb.x;
                v.y += ew0.y + ew1.y + wv.y + sw0.y + sw1.y + lb.y;
                v.z += ew0.z + ew1.z + wv.z + sw0.z + sw1.z + lb.z;
                v.w += ew0.w + ew1.w + wv.w + sw0.w + sw1.w + lb.w;
                *reinterpret_cast<float4*>(&obase[e * 16 + cq]) = v;
            }
        }
    }
}

// ---------------------------------------------------------------------------
__global__ void prep_all(const float* __restrict__ fh, const float* __restrict__ fv,
                         const float* __restrict__ sW, const float* __restrict__ eW,
                         const float* __restrict__ U)
{
    const int i = blockIdx.x * 256 + threadIdx.x;
    float4 v;
    __half* dst;
    size_t o;
    if (i < 51200) {
        v = reinterpret_cast<const float4*>(sW)[i];
        dst = g_sW16; o = (size_t)i * 4;
    } else if (i < 102400) {
        const int j = i - 51200;
        v = reinterpret_cast<const float4*>(eW)[j];
        dst = g_eW16; o = (size_t)j * 4;
    } else if (i < 364544) {
        const int j = i - 102400;
        v = reinterpret_cast<const float4*>(U)[j];
        dst = g_U16; o = (size_t)j * 4;
    } else {
        const int j = i - 364544;
        const int row = j / 200, c4 = j % 200;
        if (c4 < 192) v = reinterpret_cast<const float4*>(fh)[row * 192 + c4];
        else          v = reinterpret_cast<const float4*>(fv)[row * 8 + (c4 - 192)];
        dst = g_x; o = (size_t)row * HF + c4 * 4;
    }
    *reinterpret_cast<uint2*>(&dst[o]) = make_uint2(pkh2(v.x, v.y), pkh2(v.z, v.w));
}

// ---------------------------------------------------------------------------
__global__ void wh_proj(const float* __restrict__ wh, const float* __restrict__ linW) {
    __shared__ float tileS[64 * WDd];
    __shared__ float WwS[WDd * Cc];
    const int tid = threadIdx.x;
    const int p0 = blockIdx.x * 64;
    {
        float4 a = reinterpret_cast<const float4*>(linW + 2 * Tt * Cc)[tid];
        *reinterpret_cast<float4*>(&WwS[tid * 4]) = a;
        const float4* src = reinterpret_cast<const float4*>(wh + (size_t)p0 * WDd);
#pragma unroll
        for (int l = 0; l < 4; l++) {
            float4 b = src[tid + l * 256];
            *reinterpret_cast<float4*>(&tileS[(tid + l * 256) * 4]) = b;
        }
    }
    __syncthreads();
    const int c = tid & 15, pl0 = (tid >> 4) * 4;
#pragma unroll
    for (int r = 0; r < 4; r++) {
        const int pl = pl0 + r;
        float acc = 0.f;
#pragma unroll
        for (int w = 0; w < WDd; w++)
            acc += tileS[pl * WDd + w] * WwS[w * Cc + c];
        g_whWw[(p0 + pl) * Cc + c] = acc;
    }
}

// ------------------------------- launch
extern "C" void kernel_launch(void* const* d_in, const int* in_sizes, int n_in,
                              void* d_out, int out_size)
{
    const float* fh   = (const float*)d_in[0];
    const float* fv   = (const float*)d_in[1];
    const float* sW   = (const float*)d_in[2];
    const float* sb   = (const float*)d_in[3];
    const float* eW   = (const float*)d_in[4];
    const float* eb   = (const float*)d_in[5];
    const float* U    = (const float*)d_in[6];
    const float* wh   = (const float*)d_in[7];
    const float* linW = (const float*)d_in[8];
    const float* linb = (const float*)d_in[9];
    float* out = (float*)d_out;

    // stage sizes: g0 = 32*80+32*272 = 11264 ; g1 = 128*80+32*272 = 18944 ;
    //              g2 = 128*80+128*80 = 20480
    constexpr int SMEM_G0 = STG * 11264;                 // 56320 >= 25088 staging
    constexpr int SMEM_G1 = STG * 18944;                 // 94720 >= 67584 staging
    constexpr int SMEM_G2 = STG * 20480;                 // 102400 >= 67584 staging

    cudaFuncSetAttribute(mma_gemm<32, 0, true>,   cudaFuncAttributeMaxDynamicSharedMemorySize, SMEM_G0);
    cudaFuncSetAttribute(mma_gemm<128, 1, true>,  cudaFuncAttributeMaxDynamicSharedMemorySize, SMEM_G1);
    cudaFuncSetAttribute(mma_gemm<128, 2, false>, cudaFuncAttributeMaxDynamicSharedMemorySize, SMEM_G2);

    prep_all<<<2224, 256>>>(fh, fv, sW, eW, U);
    wh_proj<<<1024, 256>>>(wh, linW);

    mma_gemm<32, 0, true><<<dim3(4, 32), 256, SMEM_G0>>>(sb, eb, (float*)linW, HF);       // s,e + proj
    mma_gemm<128, 1, true><<<dim3(32, 8), 256, SMEM_G1>>>(nullptr, nullptr, nullptr, Tt); // sU
    mma_gemm<128, 2, false><<<dim3(2, 32, 4), 256, SMEM_G2>>>(linb, nullptr, out, Tt);    // pre
}